// round 3
// baseline (speedup 1.0000x reference)
#include <cuda_runtime.h>

// ChessMultiStageAttention — persistent-CTA fused fp32, f32x2 math.
// Round 3: TPB=512 (16 warps/SM for latency hiding), LDS.128 everywhere
// (float4 K/V/Q/activation loads, 16B-aligned padded strides).

#define TPB 512
#define NBATCH 4096
typedef unsigned long long ull;

__device__ int g_next_batch;
__global__ void hx_reset_counter() { g_next_batch = 0; }

__device__ __forceinline__ ull pk2(float x, float y) {
    ull r; asm("mov.b64 %0,{%1,%2};" : "=l"(r) : "f"(x), "f"(y)); return r;
}
__device__ __forceinline__ void up2(ull p, float& x, float& y) {
    asm("mov.b64 {%0,%1},%2;" : "=f"(x), "=f"(y) : "l"(p));
}
__device__ __forceinline__ ull fma2_(ull a, ull b, ull c) {
    ull d; asm("fma.rn.f32x2 %0,%1,%2,%3;" : "=l"(d) : "l"(a), "l"(b), "l"(c)); return d;
}
__device__ __forceinline__ ull mul2_(ull a, ull b) {
    ull d; asm("mul.rn.f32x2 %0,%1,%2;" : "=l"(d) : "l"(a), "l"(b)); return d;
}
__device__ __forceinline__ float ex2_(float x) {
    float r; asm("ex2.approx.f32 %0,%1;" : "=f"(r) : "f"(x)); return r;
}

#define LOG2E 1.4426950408889634f
#define KSCALE (0.35355339059327373f * 1.4426950408889634f)

extern "C" __global__ void __launch_bounds__(TPB)
chess_attn_kernel(const float* __restrict__ gx,
                  const float* __restrict__ gpos,
                  const float* __restrict__ ggamma,
                  const float* __restrict__ gbeta,
                  const float* __restrict__ gqkvw,   // [192,64]
                  const float* __restrict__ gqkvb,   // [192]
                  const float* __restrict__ goutw,   // [64,64]
                  const float* __restrict__ goutb,   // [64]
                  const float* __restrict__ gcb,     // [64,64]
                  float* __restrict__ gout)
{
    extern __shared__ float sm[];
    float* sm_qkv = sm;                  // 64*196 = 12544 (qkv; later y-buffer)
    float* sm_w2f = sm_qkv + 12544;      // 64*192 = 12288  w2f[e][j] = qkv_w[j][e]
    float* sm_xT  = sm_w2f + 12288;      // 64*68  = 4352   x+pos [s][e] (residual)
    float* sm_xn  = sm_xT  + 4352;       // 4352            LN output [s][e]
    float* sm_ao  = sm_xn  + 4352;       // 4352            attn out [s][e]
    float* sm_cb  = sm_ao  + 4352;       // 64*65 = 4160    chess bias * log2e
    float* sm_owf = sm_cb  + 4160;       // 4096            owf[t][e] = out_w[e][t]
    float* sm_pos = sm_owf + 4096;       // 4096
    float* sm_qb  = sm_pos + 4096;       // 192
    float* sm_ob  = sm_qb  + 192;        // 64
    float* sm_g   = sm_ob  + 64;         // 64
    float* sm_bt  = sm_g   + 64;         // 64
    int*   sm_bb  = (int*)(sm_bt + 64);

    ull* qkvU = (ull*)sm_qkv;            // row stride 98 ull
    ull* w2U  = (ull*)sm_w2f;            // row stride 96 ull
    ull* owU  = (ull*)sm_owf;            // row stride 32 ull
    ull* qbU  = (ull*)sm_qb;
    ull* obU  = (ull*)sm_ob;

    const int tid  = threadIdx.x;
    const int lane = tid & 31;
    const int warp = tid >> 5;
    const int tx   = tid & 15;           // col group
    const int ty   = tid >> 4;           // 0..31 row

    // ---- stage constants ----
    for (int i = tid; i < 192 * 64; i += TPB) {
        int j = i >> 6, e = i & 63;
        sm_w2f[e * 192 + j] = gqkvw[i];
    }
    for (int i = tid; i < 64 * 64; i += TPB) {
        int e = i >> 6, t = i & 63;
        sm_owf[t * 64 + e] = goutw[i];
    }
    for (int i = tid; i < 64 * 64; i += TPB) {
        int s = i >> 6, t = i & 63;
        sm_cb[s * 65 + t] = gcb[i] * LOG2E;
    }
    for (int i = tid; i < 4096; i += TPB) sm_pos[i] = gpos[i];
    if (tid < 192) sm_qb[tid] = gqkvb[tid];
    if (tid < 64) { sm_ob[tid] = goutb[tid]; sm_g[tid] = ggamma[tid]; sm_bt[tid] = gbeta[tid]; }

    while (true) {
        __syncthreads();
        if (tid == 0) sm_bb[0] = atomicAdd(&g_next_batch, 1);
        __syncthreads();
        int b = sm_bb[0];
        if (b >= NBATCH) break;
        const float4* xb4  = (const float4*)(gx + (size_t)b * 4096);
        const float4* pos4 = (const float4*)sm_pos;

        // ---- phase 1: load + pos, transpose to [s][e] ----
        for (int i4 = tid; i4 < 1024; i4 += TPB) {
            float4 xv = xb4[i4], pv = pos4[i4];
            int e = i4 >> 4, s0 = (i4 & 15) * 4;
            sm_xT[(s0 + 0) * 68 + e] = xv.x + pv.x;
            sm_xT[(s0 + 1) * 68 + e] = xv.y + pv.y;
            sm_xT[(s0 + 2) * 68 + e] = xv.z + pv.z;
            sm_xT[(s0 + 3) * 68 + e] = xv.w + pv.w;
        }
        __syncthreads();

        // ---- phase 2: LayerNorm (warp per row, 4 rows/warp) ----
        #pragma unroll
        for (int it = 0; it < 4; it++) {
            int s = it * 16 + warp;
            float v0 = sm_xT[s * 68 + lane];
            float v1 = sm_xT[s * 68 + 32 + lane];
            float sum = v0 + v1;
            float sq  = v0 * v0 + v1 * v1;
            #pragma unroll
            for (int off = 16; off; off >>= 1) {
                sum += __shfl_xor_sync(0xffffffffu, sum, off);
                sq  += __shfl_xor_sync(0xffffffffu, sq,  off);
            }
            float mu  = sum * (1.0f / 64.0f);
            float var = sq  * (1.0f / 64.0f) - mu * mu;
            float rs  = rsqrtf(var + 1e-5f);
            sm_xn[s * 68 + lane]      = (v0 - mu) * rs * sm_g[lane]      + sm_bt[lane];
            sm_xn[s * 68 + 32 + lane] = (v1 - mu) * rs * sm_g[lane + 32] + sm_bt[lane + 32];
        }
        __syncthreads();

        // ---- phase 3: QKV GEMM (f32x2, 2 rows x 6 pair-cols / thread) ----
        {
            ull acc[2][6];
            #pragma unroll
            for (int jj = 0; jj < 6; jj++) {
                ull bv = qbU[tx + 16 * jj];
                acc[0][jj] = bv; acc[1][jj] = bv;
            }
            #pragma unroll 2
            for (int e0 = 0; e0 < 64; e0 += 4) {
                float4 a0 = *(const float4*)(sm_xn + ty * 68 + e0);
                float4 a1 = *(const float4*)(sm_xn + (ty + 32) * 68 + e0);
                float a0v[4] = {a0.x, a0.y, a0.z, a0.w};
                float a1v[4] = {a1.x, a1.y, a1.z, a1.w};
                #pragma unroll
                for (int k = 0; k < 4; k++) {
                    int e = e0 + k;
                    ull p0 = pk2(a0v[k], a0v[k]);
                    ull p1 = pk2(a1v[k], a1v[k]);
                    ull w[6];
                    #pragma unroll
                    for (int jj = 0; jj < 6; jj++) w[jj] = w2U[e * 96 + tx + 16 * jj];
                    #pragma unroll
                    for (int jj = 0; jj < 6; jj++) {
                        acc[0][jj] = fma2_(p0, w[jj], acc[0][jj]);
                        acc[1][jj] = fma2_(p1, w[jj], acc[1][jj]);
                    }
                }
            }
            #pragma unroll
            for (int jj = 0; jj < 6; jj++) {
                qkvU[ty * 98 + tx + 16 * jj]        = acc[0][jj];
                qkvU[(ty + 32) * 98 + tx + 16 * jj] = acc[1][jj];
            }
        }
        __syncthreads();

        // ---- phase 4: attention, one (head,row) per thread, float4 loads ----
        {
            int h = tid >> 6, s = tid & 63;
            const float4* qp = (const float4*)(qkvU + s * 98 + h * 4);
            float4 qa = qp[0], qb_ = qp[1];
            ull q0 = pk2(qa.x, qa.y), q1 = pk2(qa.z, qa.w);
            ull q2 = pk2(qb_.x, qb_.y), q3 = pk2(qb_.z, qb_.w);
            const float* cbp = sm_cb + s * 65;
            float sums[4] = {0.f, 0.f, 0.f, 0.f};
            ull a0 = 0, a1 = 0, a2 = 0, a3 = 0;
            #pragma unroll 4
            for (int t = 0; t < 64; t++) {
                const float4* kp = (const float4*)(qkvU + t * 98 + 32 + h * 4);
                float4 ka = kp[0], kb = kp[1];
                ull d2 = mul2_(q0, pk2(ka.x, ka.y));
                d2 = fma2_(q1, pk2(ka.z, ka.w), d2);
                d2 = fma2_(q2, pk2(kb.x, kb.y), d2);
                d2 = fma2_(q3, pk2(kb.z, kb.w), d2);
                float dl, dh; up2(d2, dl, dh);
                float p = ex2_(fmaf(dl + dh, KSCALE, cbp[t]));
                sums[t & 3] += p;
                ull pp = pk2(p, p);
                const float4* vp = (const float4*)(qkvU + t * 98 + 64 + h * 4);
                float4 va = vp[0], vb = vp[1];
                a0 = fma2_(pp, pk2(va.x, va.y), a0);
                a1 = fma2_(pp, pk2(va.z, va.w), a1);
                a2 = fma2_(pp, pk2(vb.x, vb.y), a2);
                a3 = fma2_(pp, pk2(vb.z, vb.w), a3);
            }
            float inv = 1.0f / ((sums[0] + sums[1]) + (sums[2] + sums[3]));
            ull iv = pk2(inv, inv);
            ull* aor = (ull*)(sm_ao + s * 68) + h * 4;
            aor[0] = mul2_(a0, iv);
            aor[1] = mul2_(a1, iv);
            aor[2] = mul2_(a2, iv);
            aor[3] = mul2_(a3, iv);
        }
        __syncthreads();

        // ---- phase 5: out-proj (2 rows x 2 pair-cols / thread), y -> sm_qkv ----
        {
            ull acc[2][2];
            ull b0 = obU[tx], b1 = obU[tx + 16];
            acc[0][0] = b0; acc[0][1] = b1; acc[1][0] = b0; acc[1][1] = b1;
            #pragma unroll 2
            for (int t0 = 0; t0 < 64; t0 += 4) {
                float4 a0 = *(const float4*)(sm_ao + ty * 68 + t0);
                float4 a1 = *(const float4*)(sm_ao + (ty + 32) * 68 + t0);
                float a0v[4] = {a0.x, a0.y, a0.z, a0.w};
                float a1v[4] = {a1.x, a1.y, a1.z, a1.w};
                #pragma unroll
                for (int k = 0; k < 4; k++) {
                    int t = t0 + k;
                    ull w0 = owU[t * 32 + tx], w1 = owU[t * 32 + tx + 16];
                    ull p0 = pk2(a0v[k], a0v[k]);
                    ull p1 = pk2(a1v[k], a1v[k]);
                    acc[0][0] = fma2_(p0, w0, acc[0][0]);
                    acc[0][1] = fma2_(p0, w1, acc[0][1]);
                    acc[1][0] = fma2_(p1, w0, acc[1][0]);
                    acc[1][1] = fma2_(p1, w1, acc[1][1]);
                }
            }
            qkvU[ty * 98 + tx]             = acc[0][0];
            qkvU[ty * 98 + tx + 16]        = acc[0][1];
            qkvU[(ty + 32) * 98 + tx]      = acc[1][0];
            qkvU[(ty + 32) * 98 + tx + 16] = acc[1][1];
        }
        __syncthreads();

        // ---- phase 6: residual + transpose back, float4 stores ----
        float4* ob4 = (float4*)(gout + (size_t)b * 4096);
        for (int i4 = tid; i4 < 1024; i4 += TPB) {
            int e = i4 >> 4, s0 = (i4 & 15) * 4;
            float4 o;
            o.x = sm_xT[(s0 + 0) * 68 + e] + sm_qkv[(s0 + 0) * 196 + e];
            o.y = sm_xT[(s0 + 1) * 68 + e] + sm_qkv[(s0 + 1) * 196 + e];
            o.z = sm_xT[(s0 + 2) * 68 + e] + sm_qkv[(s0 + 2) * 196 + e];
            o.w = sm_xT[(s0 + 3) * 68 + e] + sm_qkv[(s0 + 3) * 196 + e];
            ob4[i4] = o;
        }
    }
}

static const int SMEM_FLOATS = 12544 + 12288 + 4352 * 3 + 4160 + 4096 + 4096
                             + 192 + 64 + 64 + 64;
static const int SMEM_BYTES  = SMEM_FLOATS * 4 + 16;

extern "C" void kernel_launch(void* const* d_in, const int* in_sizes, int n_in,
                              void* d_out, int out_size)
{
    (void)in_sizes; (void)n_in; (void)out_size;
    cudaFuncSetAttribute(chess_attn_kernel,
                         cudaFuncAttributeMaxDynamicSharedMemorySize, SMEM_BYTES);
    hx_reset_counter<<<1, 1>>>();
    chess_attn_kernel<<<152, TPB, SMEM_BYTES>>>(
        (const float*)d_in[0], (const float*)d_in[1], (const float*)d_in[2],
        (const float*)d_in[3], (const float*)d_in[4], (const float*)d_in[5],
        (const float*)d_in[6], (const float*)d_in[7], (const float*)d_in[8],
        (float*)d_out);
}

// round 4
// speedup vs baseline: 1.1347x; 1.1347x over previous
#include <cuda_runtime.h>

// ChessMultiStageAttention — persistent-CTA fused fp32, f32x2 math.
// Round 4: smem slot-cycle minimization. Odd (65) strides kill transpose bank
// conflicts; phase-3 weights loaded fully-distinct across lanes; attention
// streams K/V once per head (8 warps, 2 s-rows/thread).

#define TPB 512
#define NBATCH 4096
typedef unsigned long long ull;

__device__ int g_next_batch;
__global__ void hx_reset_counter() { g_next_batch = 0; }

__device__ __forceinline__ ull pk2(float x, float y) {
    ull r; asm("mov.b64 %0,{%1,%2};" : "=l"(r) : "f"(x), "f"(y)); return r;
}
__device__ __forceinline__ void up2(ull p, float& x, float& y) {
    asm("mov.b64 {%0,%1},%2;" : "=f"(x), "=f"(y) : "l"(p));
}
__device__ __forceinline__ ull fma2_(ull a, ull b, ull c) {
    ull d; asm("fma.rn.f32x2 %0,%1,%2,%3;" : "=l"(d) : "l"(a), "l"(b), "l"(c)); return d;
}
__device__ __forceinline__ ull mul2_(ull a, ull b) {
    ull d; asm("mul.rn.f32x2 %0,%1,%2;" : "=l"(d) : "l"(a), "l"(b)); return d;
}
__device__ __forceinline__ float ex2_(float x) {
    float r; asm("ex2.approx.f32 %0,%1;" : "=f"(r) : "f"(x)); return r;
}

#define LOG2E 1.4426950408889634f
#define KSCALE (0.35355339059327373f * 1.4426950408889634f)

extern "C" __global__ void __launch_bounds__(TPB)
chess_attn_kernel(const float* __restrict__ gx,
                  const float* __restrict__ gpos,
                  const float* __restrict__ ggamma,
                  const float* __restrict__ gbeta,
                  const float* __restrict__ gqkvw,   // [192,64]
                  const float* __restrict__ gqkvb,   // [192]
                  const float* __restrict__ goutw,   // [64,64]
                  const float* __restrict__ goutb,   // [64]
                  const float* __restrict__ gcb,     // [64,64]
                  float* __restrict__ gout)
{
    extern __shared__ float sm[];
    float* sm_qkv = sm;                  // 64*196 = 12544 (stride 196 fl / 98 ull)
    float* sm_w2f = sm_qkv + 12544;      // 64*192 = 12288  w2f[e][j] = qkv_w[j][e]
    float* sm_xT  = sm_w2f + 12288;      // 64*65  = 4160   x+pos [s][e], stride 65
    float* sm_xn  = sm_xT  + 4160;       // 64*68  = 4352   LN out, stride 68 (float4)
    float* sm_ao  = sm_xn  + 4352;       // 64*65  = 4160   attn out, stride 65
    float* sm_cb  = sm_ao  + 4160;       // 64*65  = 4160   chess bias * log2e
    float* sm_owf = sm_cb  + 4160;       // 4096            owf[t][e] = out_w[e][t]
    float* sm_pos = sm_owf + 4096;       // 4096
    float* sm_qb  = sm_pos + 4096;       // 192
    float* sm_ob  = sm_qb  + 192;        // 64
    float* sm_g   = sm_ob  + 64;         // 64
    float* sm_bt  = sm_g   + 64;         // 64
    int*   sm_bb  = (int*)(sm_bt + 64);
    float* sm_y   = sm_xn;               // y reuses xn buffer, stride 65

    ull* qkvU = (ull*)sm_qkv;            // row stride 98 ull
    ull* w2U  = (ull*)sm_w2f;            // row stride 96 ull (pair index = j/2)
    ull* owU  = (ull*)sm_owf;            // row stride 32 ull
    ull* qbU  = (ull*)sm_qb;
    ull* obU  = (ull*)sm_ob;

    const int tid  = threadIdx.x;
    const int lane = tid & 31;
    const int warp = tid >> 5;
    const int tx   = tid & 15;
    const int ty   = tid >> 4;           // 0..31

    // ---- stage constants ----
    for (int i = tid; i < 192 * 64; i += TPB) {
        int j = i >> 6, e = i & 63;
        sm_w2f[e * 192 + j] = gqkvw[i];
    }
    for (int i = tid; i < 64 * 64; i += TPB) {
        int e = i >> 6, t = i & 63;
        sm_owf[t * 64 + e] = goutw[i];
    }
    for (int i = tid; i < 64 * 64; i += TPB) {
        int s = i >> 6, t = i & 63;
        sm_cb[s * 65 + t] = gcb[i] * LOG2E;
    }
    for (int i = tid; i < 4096; i += TPB) sm_pos[i] = gpos[i];
    if (tid < 192) sm_qb[tid] = gqkvb[tid];
    if (tid < 64) { sm_ob[tid] = goutb[tid]; sm_g[tid] = ggamma[tid]; sm_bt[tid] = gbeta[tid]; }

    while (true) {
        __syncthreads();
        if (tid == 0) sm_bb[0] = atomicAdd(&g_next_batch, 1);
        __syncthreads();
        int b = sm_bb[0];
        if (b >= NBATCH) break;
        const float4* xb4  = (const float4*)(gx + (size_t)b * 4096);
        const float4* pos4 = (const float4*)sm_pos;

        // ---- phase 1: load + pos, transpose to [s][e] (stride 65) ----
        for (int i4 = tid; i4 < 1024; i4 += TPB) {
            float4 xv = xb4[i4], pv = pos4[i4];
            int e = i4 >> 4, s0 = (i4 & 15) * 4;
            sm_xT[(s0 + 0) * 65 + e] = xv.x + pv.x;
            sm_xT[(s0 + 1) * 65 + e] = xv.y + pv.y;
            sm_xT[(s0 + 2) * 65 + e] = xv.z + pv.z;
            sm_xT[(s0 + 3) * 65 + e] = xv.w + pv.w;
        }
        __syncthreads();

        // ---- phase 2: LayerNorm (warp per row) -> xn stride 68 ----
        #pragma unroll
        for (int it = 0; it < 4; it++) {
            int s = it * 16 + warp;
            float v0 = sm_xT[s * 65 + lane];
            float v1 = sm_xT[s * 65 + 32 + lane];
            float sum = v0 + v1;
            float sq  = v0 * v0 + v1 * v1;
            #pragma unroll
            for (int off = 16; off; off >>= 1) {
                sum += __shfl_xor_sync(0xffffffffu, sum, off);
                sq  += __shfl_xor_sync(0xffffffffu, sq,  off);
            }
            float mu  = sum * (1.0f / 64.0f);
            float var = sq  * (1.0f / 64.0f) - mu * mu;
            float rs  = rsqrtf(var + 1e-5f);
            sm_xn[s * 68 + lane]      = (v0 - mu) * rs * sm_g[lane]      + sm_bt[lane];
            sm_xn[s * 68 + 32 + lane] = (v1 - mu) * rs * sm_g[lane + 32] + sm_bt[lane + 32];
        }
        __syncthreads();

        // ---- phase 3: QKV GEMM. warp = 4 rows x 96 pairs; lane owns pairs
        //      {lane, lane+32, lane+64} -> weight LDS.64 fully distinct ----
        {
            const int r0 = warp * 4;
            ull acc[4][3];
            #pragma unroll
            for (int m = 0; m < 3; m++) {
                ull bv = qbU[lane + 32 * m];
                #pragma unroll
                for (int i = 0; i < 4; i++) acc[i][m] = bv;
            }
            #pragma unroll 2
            for (int e0 = 0; e0 < 64; e0 += 4) {
                float a4[4][4];
                #pragma unroll
                for (int i = 0; i < 4; i++) {
                    float4 v = *(const float4*)(sm_xn + (r0 + i) * 68 + e0);
                    a4[i][0] = v.x; a4[i][1] = v.y; a4[i][2] = v.z; a4[i][3] = v.w;
                }
                #pragma unroll
                for (int k = 0; k < 4; k++) {
                    int e = e0 + k;
                    ull w0 = w2U[e * 96 + lane];
                    ull w1 = w2U[e * 96 + lane + 32];
                    ull w2 = w2U[e * 96 + lane + 64];
                    #pragma unroll
                    for (int i = 0; i < 4; i++) {
                        ull ap = pk2(a4[i][k], a4[i][k]);
                        acc[i][0] = fma2_(ap, w0, acc[i][0]);
                        acc[i][1] = fma2_(ap, w1, acc[i][1]);
                        acc[i][2] = fma2_(ap, w2, acc[i][2]);
                    }
                }
            }
            #pragma unroll
            for (int i = 0; i < 4; i++)
                #pragma unroll
                for (int m = 0; m < 3; m++)
                    qkvU[(r0 + i) * 98 + lane + 32 * m] = acc[i][m];
        }
        __syncthreads();

        // ---- phase 4: attention. 8 warps, warp = head, 2 s-rows/thread:
        //      K/V broadcast-streamed ONCE per head ----
        if (warp < 8) {
            const int h = warp;
            const int sA = lane, sB = lane + 32;
            const ulonglong2* qpA = (const ulonglong2*)(qkvU + sA * 98 + h * 4);
            const ulonglong2* qpB = (const ulonglong2*)(qkvU + sB * 98 + h * 4);
            ulonglong2 qa0 = qpA[0], qa1 = qpA[1];
            ulonglong2 qb0 = qpB[0], qb1 = qpB[1];
            const float* cbA = sm_cb + sA * 65;
            const float* cbB = sm_cb + sB * 65;
            ull accA[4] = {0, 0, 0, 0}, accB[4] = {0, 0, 0, 0};
            float smA[2] = {0.f, 0.f}, smB[2] = {0.f, 0.f};
            #pragma unroll 4
            for (int t = 0; t < 64; t++) {
                const ulonglong2* kp = (const ulonglong2*)(qkvU + t * 98 + 32 + h * 4);
                ulonglong2 k0 = kp[0], k1 = kp[1];
                ull dA = mul2_(qa0.x, k0.x);
                dA = fma2_(qa0.y, k0.y, dA);
                dA = fma2_(qa1.x, k1.x, dA);
                dA = fma2_(qa1.y, k1.y, dA);
                ull dB = mul2_(qb0.x, k0.x);
                dB = fma2_(qb0.y, k0.y, dB);
                dB = fma2_(qb1.x, k1.x, dB);
                dB = fma2_(qb1.y, k1.y, dB);
                float al, ah, bl, bh;
                up2(dA, al, ah); up2(dB, bl, bh);
                float pA = ex2_(fmaf(al + ah, KSCALE, cbA[t]));
                float pB = ex2_(fmaf(bl + bh, KSCALE, cbB[t]));
                smA[t & 1] += pA; smB[t & 1] += pB;
                ull ppA = pk2(pA, pA), ppB = pk2(pB, pB);
                const ulonglong2* vp = (const ulonglong2*)(qkvU + t * 98 + 64 + h * 4);
                ulonglong2 v0 = vp[0], v1 = vp[1];
                accA[0] = fma2_(ppA, v0.x, accA[0]);
                accA[1] = fma2_(ppA, v0.y, accA[1]);
                accA[2] = fma2_(ppA, v1.x, accA[2]);
                accA[3] = fma2_(ppA, v1.y, accA[3]);
                accB[0] = fma2_(ppB, v0.x, accB[0]);
                accB[1] = fma2_(ppB, v0.y, accB[1]);
                accB[2] = fma2_(ppB, v1.x, accB[2]);
                accB[3] = fma2_(ppB, v1.y, accB[3]);
            }
            float invA = 1.0f / (smA[0] + smA[1]);
            float invB = 1.0f / (smB[0] + smB[1]);
            ull ivA = pk2(invA, invA), ivB = pk2(invB, invB);
            float* aoA = sm_ao + sA * 65 + h * 8;
            float* aoB = sm_ao + sB * 65 + h * 8;
            #pragma unroll
            for (int d = 0; d < 4; d++) {
                float lo, hi;
                up2(mul2_(accA[d], ivA), lo, hi);
                aoA[2 * d] = lo; aoA[2 * d + 1] = hi;
                up2(mul2_(accB[d], ivB), lo, hi);
                aoB[2 * d] = lo; aoB[2 * d + 1] = hi;
            }
        }
        __syncthreads();

        // ---- phase 5: out-proj. thread (tx,ty): rows {ty,ty+32}, pairs {tx,tx+16}
        //      -> y (stride 65, reuses xn buffer) ----
        {
            ull acc00, acc01, acc10, acc11;
            ull b0 = obU[tx], b1 = obU[tx + 16];
            acc00 = b0; acc01 = b1; acc10 = b0; acc11 = b1;
            const float* aoA = sm_ao + ty * 65;
            const float* aoB = sm_ao + (ty + 32) * 65;
            #pragma unroll 4
            for (int t = 0; t < 64; t++) {
                float a0 = aoA[t], a1 = aoB[t];
                ull w0 = owU[t * 32 + tx], w1 = owU[t * 32 + tx + 16];
                ull p0 = pk2(a0, a0), p1 = pk2(a1, a1);
                acc00 = fma2_(p0, w0, acc00);
                acc01 = fma2_(p0, w1, acc01);
                acc10 = fma2_(p1, w0, acc10);
                acc11 = fma2_(p1, w1, acc11);
            }
            float lo, hi;
            float* y0 = sm_y + ty * 65;
            float* y1 = sm_y + (ty + 32) * 65;
            up2(acc00, lo, hi); y0[2 * tx] = lo;      y0[2 * tx + 1] = hi;
            up2(acc01, lo, hi); y0[2 * tx + 32] = lo; y0[2 * tx + 33] = hi;
            up2(acc10, lo, hi); y1[2 * tx] = lo;      y1[2 * tx + 1] = hi;
            up2(acc11, lo, hi); y1[2 * tx + 32] = lo; y1[2 * tx + 33] = hi;
        }
        __syncthreads();

        // ---- phase 6: residual + transpose back, float4 stores ----
        float4* ob4 = (float4*)(gout + (size_t)b * 4096);
        for (int i4 = tid; i4 < 1024; i4 += TPB) {
            int e = i4 >> 4, s0 = (i4 & 15) * 4;
            float4 o;
            o.x = sm_xT[(s0 + 0) * 65 + e] + sm_y[(s0 + 0) * 65 + e];
            o.y = sm_xT[(s0 + 1) * 65 + e] + sm_y[(s0 + 1) * 65 + e];
            o.z = sm_xT[(s0 + 2) * 65 + e] + sm_y[(s0 + 2) * 65 + e];
            o.w = sm_xT[(s0 + 3) * 65 + e] + sm_y[(s0 + 3) * 65 + e];
            ob4[i4] = o;
        }
    }
}

static const int SMEM_FLOATS = 12544 + 12288 + 4160 + 4352 + 4160 + 4160 + 4096 + 4096
                             + 192 + 64 + 64 + 64;
static const int SMEM_BYTES  = SMEM_FLOATS * 4 + 16;

extern "C" void kernel_launch(void* const* d_in, const int* in_sizes, int n_in,
                              void* d_out, int out_size)
{
    (void)in_sizes; (void)n_in; (void)out_size;
    cudaFuncSetAttribute(chess_attn_kernel,
                         cudaFuncAttributeMaxDynamicSharedMemorySize, SMEM_BYTES);
    hx_reset_counter<<<1, 1>>>();
    chess_attn_kernel<<<152, TPB, SMEM_BYTES>>>(
        (const float*)d_in[0], (const float*)d_in[1], (const float*)d_in[2],
        (const float*)d_in[3], (const float*)d_in[4], (const float*)d_in[5],
        (const float*)d_in[6], (const float*)d_in[7], (const float*)d_in[8],
        (float*)d_out);
}

// round 5
// speedup vs baseline: 1.3329x; 1.1746x over previous
#include <cuda_runtime.h>

// ChessMultiStageAttention — persistent CTA, two independent 256-thread
// pipelines per CTA (named barriers), f32x2 math, conflict-free smem layouts.

#define TPB 512
#define NBATCH 4096
typedef unsigned long long ull;

__device__ int g_next_batch;
__global__ void hx_reset_counter() { g_next_batch = 0; }

__device__ __forceinline__ ull pk2(float x, float y) {
    ull r; asm("mov.b64 %0,{%1,%2};" : "=l"(r) : "f"(x), "f"(y)); return r;
}
__device__ __forceinline__ void up2(ull p, float& x, float& y) {
    asm("mov.b64 {%0,%1},%2;" : "=f"(x), "=f"(y) : "l"(p));
}
__device__ __forceinline__ ull fma2_(ull a, ull b, ull c) {
    ull d; asm("fma.rn.f32x2 %0,%1,%2,%3;" : "=l"(d) : "l"(a), "l"(b), "l"(c)); return d;
}
__device__ __forceinline__ ull mul2_(ull a, ull b) {
    ull d; asm("mul.rn.f32x2 %0,%1,%2;" : "=l"(d) : "l"(a), "l"(b)); return d;
}
__device__ __forceinline__ float ex2_(float x) {
    float r; asm("ex2.approx.f32 %0,%1;" : "=f"(r) : "f"(x)); return r;
}
__device__ __forceinline__ void hbar(int half) {
    asm volatile("bar.sync %0, 256;" :: "r"(1 + half) : "memory");
}

#define LOG2E 1.4426950408889634f
#define KSCALE (0.35355339059327373f * 1.4426950408889634f)

// smem offsets in floats
#define OFF_W2F  0                    // 12288  w2f[e][j] = qkv_w[j][e]
#define OFF_OWF  12288                // 4096   owf[t][e] = out_w[e][t]
#define OFF_CB   16384                // 4160   cb[s*65+t] * log2e
#define OFF_QB   20544                // 192
#define OFF_OB   20736                // 64
#define OFF_G    20800                // 64
#define OFF_BT   20864                // 64
#define OFF_POS  20928                // 4096
#define OFF_BB   25024                // 8 (2 int slots)
#define OFF_QKV0 25032                // 12288 each half (ull stride 96)
#define OFF_QKV1 37320
#define OFF_XB0  49608                // 4160 each half ([e][s] / ao [s][e], stride 65)
#define OFF_XB1  53768
#define SMEM_FLOATS 57928
#define SMEM_BYTES  (SMEM_FLOATS * 4)

extern "C" __global__ void __launch_bounds__(TPB)
chess_attn_kernel(const float* __restrict__ gx,
                  const float* __restrict__ gpos,
                  const float* __restrict__ ggamma,
                  const float* __restrict__ gbeta,
                  const float* __restrict__ gqkvw,
                  const float* __restrict__ gqkvb,
                  const float* __restrict__ goutw,
                  const float* __restrict__ goutb,
                  const float* __restrict__ gcb,
                  float* __restrict__ gout)
{
    extern __shared__ float sm[];
    float* sm_w2f = sm + OFF_W2F;
    float* sm_owf = sm + OFF_OWF;
    float* sm_cb  = sm + OFF_CB;
    float* sm_qb  = sm + OFF_QB;
    float* sm_ob  = sm + OFF_OB;
    float* sm_g   = sm + OFF_G;
    float* sm_bt  = sm + OFF_BT;
    float* sm_pos = sm + OFF_POS;
    int*   sm_bb  = (int*)(sm + OFF_BB);

    const int tid  = threadIdx.x;
    const int lane = tid & 31;
    const int warp = tid >> 5;
    const int half = warp >> 3;          // 0 or 1
    const int tidh = tid & 255;          // 0..255 within half
    const int wh   = warp & 7;           // warp index within half
    const int tx   = tidh & 15;
    const int ty   = tidh >> 4;          // 0..15

    float* xb_  = sm + (half ? OFF_XB1 : OFF_XB0);   // [e][s] stride 65; later ao [s][e]
    float* qkvf = sm + (half ? OFF_QKV1 : OFF_QKV0);
    ull*   qkvU = (ull*)qkvf;                        // row stride 96 ull
    float* yT   = qkvf;                              // [e][s] stride 65 (reuses qkv)
    ull*   w2U  = (ull*)sm_w2f;                      // row stride 96 ull
    ull*   owU  = (ull*)sm_owf;                      // row stride 32 ull
    ull*   qbU  = (ull*)sm_qb;
    ull*   obU  = (ull*)sm_ob;

    // ---- stage constants (full block) ----
    for (int i = tid; i < 192 * 64; i += TPB) {
        int j = i >> 6, e = i & 63;
        sm_w2f[e * 192 + j] = gqkvw[i];
    }
    for (int i = tid; i < 64 * 64; i += TPB) {
        int e = i >> 6, t = i & 63;
        sm_owf[t * 64 + e] = goutw[i];
    }
    for (int i = tid; i < 64 * 64; i += TPB) {
        int s = i >> 6, t = i & 63;
        sm_cb[s * 65 + t] = gcb[i] * LOG2E;
    }
    for (int i = tid; i < 4096; i += TPB) sm_pos[i] = gpos[i];
    if (tid < 192) sm_qb[tid] = gqkvb[tid];
    if (tid < 64) { sm_ob[tid] = goutb[tid]; sm_g[tid] = ggamma[tid]; sm_bt[tid] = gbeta[tid]; }
    __syncthreads();

    const float4* pos4 = (const float4*)sm_pos;

    while (true) {
        hbar(half);                         // protect buffers + bb slot reuse
        if (tidh == 0) sm_bb[half] = atomicAdd(&g_next_batch, 1);
        hbar(half);
        int b = sm_bb[half];
        if (b >= NBATCH) break;
        const float4* xb4 = (const float4*)(gx + (size_t)b * 4096);

        // ---- phase 1: x + pos into xb_ [e][s] (stride 65) ----
        for (int i4 = tidh; i4 < 1024; i4 += 256) {
            float4 xv = xb4[i4], pv = pos4[i4];
            int e = i4 >> 4, s0 = (i4 & 15) * 4;
            float* p = xb_ + e * 65 + s0;
            p[0] = xv.x + pv.x;
            p[1] = xv.y + pv.y;
            p[2] = xv.z + pv.z;
            p[3] = xv.w + pv.w;
        }
        hbar(half);

        // ---- phase 2: LayerNorm in-place over e (warp per column pair) ----
        #pragma unroll
        for (int k = 0; k < 4; k++) {
            int s0 = wh * 8 + 2 * k, s1 = s0 + 1;
            float a0 = xb_[lane * 65 + s0];
            float a1 = xb_[(lane + 32) * 65 + s0];
            float b0 = xb_[lane * 65 + s1];
            float b1 = xb_[(lane + 32) * 65 + s1];
            float sa = a0 + a1, qa = a0 * a0 + a1 * a1;
            float sb = b0 + b1, qb2 = b0 * b0 + b1 * b1;
            #pragma unroll
            for (int off = 16; off; off >>= 1) {
                sa  += __shfl_xor_sync(0xffffffffu, sa,  off);
                qa  += __shfl_xor_sync(0xffffffffu, qa,  off);
                sb  += __shfl_xor_sync(0xffffffffu, sb,  off);
                qb2 += __shfl_xor_sync(0xffffffffu, qb2, off);
            }
            float muA = sa * (1.0f / 64.0f);
            float rsA = rsqrtf(qa * (1.0f / 64.0f) - muA * muA + 1e-5f);
            float muB = sb * (1.0f / 64.0f);
            float rsB = rsqrtf(qb2 * (1.0f / 64.0f) - muB * muB + 1e-5f);
            float g0 = sm_g[lane], g1 = sm_g[lane + 32];
            float t0 = sm_bt[lane], t1 = sm_bt[lane + 32];
            xb_[lane * 65 + s0]        = (a0 - muA) * rsA * g0 + t0;
            xb_[(lane + 32) * 65 + s0] = (a1 - muA) * rsA * g1 + t1;
            xb_[lane * 65 + s1]        = (b0 - muB) * rsB * g0 + t0;
            xb_[(lane + 32) * 65 + s1] = (b1 - muB) * rsB * g1 + t1;
        }
        hbar(half);

        // ---- phase 3: QKV GEMM. thread (tx,ty): rows ty+16ss, pairs tx+16jj ----
        {
            ull acc[4][6];
            #pragma unroll
            for (int jj = 0; jj < 6; jj++) {
                ull bv = qbU[tx + 16 * jj];
                #pragma unroll
                for (int ss = 0; ss < 4; ss++) acc[ss][jj] = bv;
            }
            #pragma unroll 4
            for (int e = 0; e < 64; e++) {
                ull ap[4], w[6];
                #pragma unroll
                for (int ss = 0; ss < 4; ss++) {
                    float a = xb_[e * 65 + ty + 16 * ss];   // 2 distinct addrs/warp
                    ap[ss] = pk2(a, a);
                }
                #pragma unroll
                for (int jj = 0; jj < 6; jj++) w[jj] = w2U[e * 96 + tx + 16 * jj];
                #pragma unroll
                for (int ss = 0; ss < 4; ss++)
                    #pragma unroll
                    for (int jj = 0; jj < 6; jj++)
                        acc[ss][jj] = fma2_(ap[ss], w[jj], acc[ss][jj]);
            }
            #pragma unroll
            for (int ss = 0; ss < 4; ss++)
                #pragma unroll
                for (int jj = 0; jj < 6; jj++)
                    qkvU[(ty + 16 * ss) * 96 + tx + 16 * jj] = acc[ss][jj];
        }
        hbar(half);

        // ---- phase 4: attention. warp = head; rows lane & lane+32.
        //      K/V broadcast-streamed once per head. ao -> xb_ as [s][e]. ----
        {
            const int h = wh;
            const int sA = lane, sB = lane + 32;
            const ulonglong2* qpA = (const ulonglong2*)(qkvU + sA * 96 + h * 4);
            const ulonglong2* qpB = (const ulonglong2*)(qkvU + sB * 96 + h * 4);
            ulonglong2 qa0 = qpA[0], qa1 = qpA[1];
            ulonglong2 qb0 = qpB[0], qb1 = qpB[1];
            const float* cbA = sm_cb + sA * 65;
            const float* cbB = sm_cb + sB * 65;
            ull accA[4] = {0, 0, 0, 0}, accB[4] = {0, 0, 0, 0};
            float smA0 = 0.f, smA1 = 0.f, smB0 = 0.f, smB1 = 0.f;
            #pragma unroll 4
            for (int t = 0; t < 64; t++) {
                const ulonglong2* kp = (const ulonglong2*)(qkvU + t * 96 + 32 + h * 4);
                ulonglong2 k0 = kp[0], k1 = kp[1];
                ull dA = mul2_(qa0.x, k0.x);
                dA = fma2_(qa0.y, k0.y, dA);
                dA = fma2_(qa1.x, k1.x, dA);
                dA = fma2_(qa1.y, k1.y, dA);
                ull dB = mul2_(qb0.x, k0.x);
                dB = fma2_(qb0.y, k0.y, dB);
                dB = fma2_(qb1.x, k1.x, dB);
                dB = fma2_(qb1.y, k1.y, dB);
                float al, ah, bl, bh;
                up2(dA, al, ah); up2(dB, bl, bh);
                float pA = ex2_(fmaf(al + ah, KSCALE, cbA[t]));
                float pB = ex2_(fmaf(bl + bh, KSCALE, cbB[t]));
                if (t & 1) { smA1 += pA; smB1 += pB; } else { smA0 += pA; smB0 += pB; }
                ull ppA = pk2(pA, pA), ppB = pk2(pB, pB);
                const ulonglong2* vp = (const ulonglong2*)(qkvU + t * 96 + 64 + h * 4);
                ulonglong2 v0 = vp[0], v1 = vp[1];
                accA[0] = fma2_(ppA, v0.x, accA[0]);
                accA[1] = fma2_(ppA, v0.y, accA[1]);
                accA[2] = fma2_(ppA, v1.x, accA[2]);
                accA[3] = fma2_(ppA, v1.y, accA[3]);
                accB[0] = fma2_(ppB, v0.x, accB[0]);
                accB[1] = fma2_(ppB, v0.y, accB[1]);
                accB[2] = fma2_(ppB, v1.x, accB[2]);
                accB[3] = fma2_(ppB, v1.y, accB[3]);
            }
            float invA = 1.0f / (smA0 + smA1);
            float invB = 1.0f / (smB0 + smB1);
            ull ivA = pk2(invA, invA), ivB = pk2(invB, invB);
            float* aoA = xb_ + sA * 65 + h * 8;
            float* aoB = xb_ + sB * 65 + h * 8;
            #pragma unroll
            for (int d = 0; d < 4; d++) {
                float lo, hi;
                up2(mul2_(accA[d], ivA), lo, hi);
                aoA[2 * d] = lo; aoA[2 * d + 1] = hi;
                up2(mul2_(accB[d], ivB), lo, hi);
                aoB[2 * d] = lo; aoB[2 * d + 1] = hi;
            }
        }
        hbar(half);

        // ---- phase 5: out-proj. rows ty+16ss, pairs {tx,tx+16}. yT[e][s]. ----
        {
            ull acc[4][2];
            ull b0 = obU[tx], b1 = obU[tx + 16];
            #pragma unroll
            for (int ss = 0; ss < 4; ss++) { acc[ss][0] = b0; acc[ss][1] = b1; }
            #pragma unroll 4
            for (int t = 0; t < 64; t++) {
                ull w0 = owU[t * 32 + tx], w1 = owU[t * 32 + tx + 16];
                #pragma unroll
                for (int ss = 0; ss < 4; ss++) {
                    float a = xb_[(ty + 16 * ss) * 65 + t];
                    ull ap = pk2(a, a);
                    acc[ss][0] = fma2_(ap, w0, acc[ss][0]);
                    acc[ss][1] = fma2_(ap, w1, acc[ss][1]);
                }
            }
            #pragma unroll
            for (int ss = 0; ss < 4; ss++) {
                int r = ty + 16 * ss;
                float lo, hi;
                up2(acc[ss][0], lo, hi);
                yT[(2 * tx) * 65 + r] = lo;
                yT[(2 * tx + 1) * 65 + r] = hi;
                up2(acc[ss][1], lo, hi);
                yT[(2 * tx + 32) * 65 + r] = lo;
                yT[(2 * tx + 33) * 65 + r] = hi;
            }
        }
        hbar(half);

        // ---- phase 6: residual (reload x) + y, coalesced float4 stores ----
        float4* ob4 = (float4*)(gout + (size_t)b * 4096);
        for (int i4 = tidh; i4 < 1024; i4 += 256) {
            float4 xv = xb4[i4], pv = pos4[i4];
            int e = i4 >> 4, s0 = (i4 & 15) * 4;
            const float* yp = yT + e * 65 + s0;
            float4 o;
            o.x = xv.x + pv.x + yp[0];
            o.y = xv.y + pv.y + yp[1];
            o.z = xv.z + pv.z + yp[2];
            o.w = xv.w + pv.w + yp[3];
            ob4[i4] = o;
        }
    }
}

extern "C" void kernel_launch(void* const* d_in, const int* in_sizes, int n_in,
                              void* d_out, int out_size)
{
    (void)in_sizes; (void)n_in; (void)out_size;
    cudaFuncSetAttribute(chess_attn_kernel,
                         cudaFuncAttributeMaxDynamicSharedMemorySize, SMEM_BYTES);
    hx_reset_counter<<<1, 1>>>();
    chess_attn_kernel<<<152, TPB, SMEM_BYTES>>>(
        (const float*)d_in[0], (const float*)d_in[1], (const float*)d_in[2],
        (const float*)d_in[3], (const float*)d_in[4], (const float*)d_in[5],
        (const float*)d_in[6], (const float*)d_in[7], (const float*)d_in[8],
        (float*)d_out);
}

// round 6
// speedup vs baseline: 1.3492x; 1.0123x over previous
#include <cuda_runtime.h>

// ChessMultiStageAttention — persistent CTA, two independent 256-thread
// pipelines (named barriers), f32x2 math.
// Round 6: lane-split attention (4 warps, 2 heads/warp, 2-addr LDS.128 K/V),
// LDS.128 weight loads in both GEMMs, paired chess-bias loads.

#define TPB 512
#define NBATCH 4096
typedef unsigned long long ull;

__device__ int g_next_batch;
__global__ void hx_reset_counter() { g_next_batch = 0; }

__device__ __forceinline__ ull pk2(float x, float y) {
    ull r; asm("mov.b64 %0,{%1,%2};" : "=l"(r) : "f"(x), "f"(y)); return r;
}
__device__ __forceinline__ void up2(ull p, float& x, float& y) {
    asm("mov.b64 {%0,%1},%2;" : "=f"(x), "=f"(y) : "l"(p));
}
__device__ __forceinline__ ull fma2_(ull a, ull b, ull c) {
    ull d; asm("fma.rn.f32x2 %0,%1,%2,%3;" : "=l"(d) : "l"(a), "l"(b), "l"(c)); return d;
}
__device__ __forceinline__ ull mul2_(ull a, ull b) {
    ull d; asm("mul.rn.f32x2 %0,%1,%2;" : "=l"(d) : "l"(a), "l"(b)); return d;
}
__device__ __forceinline__ float ex2_(float x) {
    float r; asm("ex2.approx.f32 %0,%1;" : "=f"(r) : "f"(x)); return r;
}
__device__ __forceinline__ void hbar(int half) {
    asm volatile("bar.sync %0, 256;" :: "r"(1 + half) : "memory");
}

#define LOG2E 1.4426950408889634f
#define KSCALE (0.35355339059327373f * 1.4426950408889634f)

// smem offsets in floats
#define OFF_W2F  0                    // 12288  w2f[e][j] = qkv_w[j][e]
#define OFF_OWF  12288                // 4096   owf[t][e] = out_w[e][t]
#define OFF_CB   16384                // 4224   cb[s*66+t] * log2e (stride 66)
#define OFF_QB   20608                // 192
#define OFF_OB   20800                // 64
#define OFF_G    20864                // 64
#define OFF_BT   20928                // 64
#define OFF_POS  20992                // 4096
#define OFF_BB   25088                // 8
#define OFF_QKV0 25096                // 12288 per half (ull stride 96)
#define OFF_QKV1 37384
#define OFF_XB0  49672                // 4160 per half (stride 65)
#define OFF_XB1  53832
#define SMEM_FLOATS 57992
#define SMEM_BYTES  (SMEM_FLOATS * 4)

extern "C" __global__ void __launch_bounds__(TPB)
chess_attn_kernel(const float* __restrict__ gx,
                  const float* __restrict__ gpos,
                  const float* __restrict__ ggamma,
                  const float* __restrict__ gbeta,
                  const float* __restrict__ gqkvw,
                  const float* __restrict__ gqkvb,
                  const float* __restrict__ goutw,
                  const float* __restrict__ goutb,
                  const float* __restrict__ gcb,
                  float* __restrict__ gout)
{
    extern __shared__ float sm[];
    float* sm_w2f = sm + OFF_W2F;
    float* sm_owf = sm + OFF_OWF;
    float* sm_cb  = sm + OFF_CB;
    float* sm_qb  = sm + OFF_QB;
    float* sm_ob  = sm + OFF_OB;
    float* sm_g   = sm + OFF_G;
    float* sm_bt  = sm + OFF_BT;
    float* sm_pos = sm + OFF_POS;
    int*   sm_bb  = (int*)(sm + OFF_BB);

    const int tid  = threadIdx.x;
    const int lane = tid & 31;
    const int warp = tid >> 5;
    const int half = warp >> 3;
    const int tidh = tid & 255;
    const int wh   = warp & 7;
    const int tx   = tidh & 15;
    const int ty   = tidh >> 4;          // 0..15

    float* xb_  = sm + (half ? OFF_XB1 : OFF_XB0);   // [e][s] str 65; later ao [s][e]
    float* qkvf = sm + (half ? OFF_QKV1 : OFF_QKV0);
    ull*   qkvU = (ull*)qkvf;                        // row stride 96 ull
    float* yT   = qkvf;                              // [e][s] stride 65 (reuses qkv)
    ull*   w2U  = (ull*)sm_w2f;                      // row stride 96 ull
    ull*   owU  = (ull*)sm_owf;                      // row stride 32 ull
    ull*   qbU  = (ull*)sm_qb;
    ull*   obU  = (ull*)sm_ob;

    // ---- stage constants (full block) ----
    for (int i = tid; i < 192 * 64; i += TPB) {
        int j = i >> 6, e = i & 63;
        sm_w2f[e * 192 + j] = gqkvw[i];
    }
    for (int i = tid; i < 64 * 64; i += TPB) {
        int e = i >> 6, t = i & 63;
        sm_owf[t * 64 + e] = goutw[i];
    }
    for (int i = tid; i < 64 * 64; i += TPB) {
        int s = i >> 6, t = i & 63;
        sm_cb[s * 66 + t] = gcb[i] * LOG2E;
    }
    for (int i = tid; i < 4096; i += TPB) sm_pos[i] = gpos[i];
    if (tid < 192) sm_qb[tid] = gqkvb[tid];
    if (tid < 64) { sm_ob[tid] = goutb[tid]; sm_g[tid] = ggamma[tid]; sm_bt[tid] = gbeta[tid]; }
    __syncthreads();

    const float4* pos4 = (const float4*)sm_pos;

    while (true) {
        hbar(half);
        if (tidh == 0) sm_bb[half] = atomicAdd(&g_next_batch, 1);
        hbar(half);
        int b = sm_bb[half];
        if (b >= NBATCH) break;
        const float4* xb4 = (const float4*)(gx + (size_t)b * 4096);

        // ---- phase 1: x + pos into xb_ [e][s] (stride 65) ----
        for (int i4 = tidh; i4 < 1024; i4 += 256) {
            float4 xv = xb4[i4], pv = pos4[i4];
            int e = i4 >> 4, s0 = (i4 & 15) * 4;
            float* p = xb_ + e * 65 + s0;
            p[0] = xv.x + pv.x;
            p[1] = xv.y + pv.y;
            p[2] = xv.z + pv.z;
            p[3] = xv.w + pv.w;
        }
        hbar(half);

        // ---- phase 2: LayerNorm in-place over e (warp per column pair) ----
        #pragma unroll
        for (int k = 0; k < 4; k++) {
            int s0 = wh * 8 + 2 * k, s1 = s0 + 1;
            float a0 = xb_[lane * 65 + s0];
            float a1 = xb_[(lane + 32) * 65 + s0];
            float b0 = xb_[lane * 65 + s1];
            float b1 = xb_[(lane + 32) * 65 + s1];
            float sa = a0 + a1, qa = a0 * a0 + a1 * a1;
            float sb = b0 + b1, qb2 = b0 * b0 + b1 * b1;
            #pragma unroll
            for (int off = 16; off; off >>= 1) {
                sa  += __shfl_xor_sync(0xffffffffu, sa,  off);
                qa  += __shfl_xor_sync(0xffffffffu, qa,  off);
                sb  += __shfl_xor_sync(0xffffffffu, sb,  off);
                qb2 += __shfl_xor_sync(0xffffffffu, qb2, off);
            }
            float muA = sa * (1.0f / 64.0f);
            float rsA = rsqrtf(qa * (1.0f / 64.0f) - muA * muA + 1e-5f);
            float muB = sb * (1.0f / 64.0f);
            float rsB = rsqrtf(qb2 * (1.0f / 64.0f) - muB * muB + 1e-5f);
            float g0 = sm_g[lane], g1 = sm_g[lane + 32];
            float t0 = sm_bt[lane], t1 = sm_bt[lane + 32];
            xb_[lane * 65 + s0]        = (a0 - muA) * rsA * g0 + t0;
            xb_[(lane + 32) * 65 + s0] = (a1 - muA) * rsA * g1 + t1;
            xb_[lane * 65 + s1]        = (b0 - muB) * rsB * g0 + t0;
            xb_[(lane + 32) * 65 + s1] = (b1 - muB) * rsB * g1 + t1;
        }
        hbar(half);

        // ---- phase 3: QKV GEMM. thread (tx,ty): rows ty+16ss,
        //      ull pairs {2tx+32m, 2tx+32m+1} -> LDS.128 weights/stores ----
        {
            ulonglong2 acc[4][3];
            #pragma unroll
            for (int m = 0; m < 3; m++) {
                ulonglong2 bv = *(const ulonglong2*)(qbU + 2 * tx + 32 * m);
                #pragma unroll
                for (int ss = 0; ss < 4; ss++) acc[ss][m] = bv;
            }
            #pragma unroll 4
            for (int e = 0; e < 64; e++) {
                ull ap[4];
                #pragma unroll
                for (int ss = 0; ss < 4; ss++) {
                    float a = xb_[e * 65 + ty + 16 * ss];
                    ap[ss] = pk2(a, a);
                }
                ulonglong2 w[3];
                #pragma unroll
                for (int m = 0; m < 3; m++)
                    w[m] = *(const ulonglong2*)(w2U + e * 96 + 2 * tx + 32 * m);
                #pragma unroll
                for (int ss = 0; ss < 4; ss++)
                    #pragma unroll
                    for (int m = 0; m < 3; m++) {
                        acc[ss][m].x = fma2_(ap[ss], w[m].x, acc[ss][m].x);
                        acc[ss][m].y = fma2_(ap[ss], w[m].y, acc[ss][m].y);
                    }
            }
            #pragma unroll
            for (int ss = 0; ss < 4; ss++)
                #pragma unroll
                for (int m = 0; m < 3; m++)
                    *(ulonglong2*)(qkvU + (ty + 16 * ss) * 96 + 2 * tx + 32 * m) = acc[ss][m];
        }
        hbar(half);

        // ---- phase 4: attention. 4 warps (one per SMSP); warp wh covers heads
        //      {2wh, 2wh+1}: lanes 0-15 head A, 16-31 head B, 4 s-rows/lane.
        //      K/V LDS.128 carries both heads (2 distinct addrs). ----
        if (wh < 4) {
            const int h  = 2 * wh + (lane >> 4);
            const int sl = lane & 15;
            ull q[4][4];
            #pragma unroll
            for (int r = 0; r < 4; r++) {
                const ulonglong2* qp = (const ulonglong2*)(qkvU + (sl + 16 * r) * 96 + h * 4);
                ulonglong2 qa = qp[0], qb_ = qp[1];
                q[r][0] = qa.x; q[r][1] = qa.y; q[r][2] = qb_.x; q[r][3] = qb_.y;
            }
            ull acc[4][4];
            #pragma unroll
            for (int r = 0; r < 4; r++)
                #pragma unroll
                for (int d = 0; d < 4; d++) acc[r][d] = 0;
            float sums[4] = {0.f, 0.f, 0.f, 0.f};
            #pragma unroll 2
            for (int t = 0; t < 64; t += 2) {
                ull cb2[4];
                #pragma unroll
                for (int r = 0; r < 4; r++)
                    cb2[r] = *(const ull*)(sm_cb + (sl + 16 * r) * 66 + t);
                #pragma unroll
                for (int u = 0; u < 2; u++) {
                    int tt = t + u;
                    const ulonglong2* kp = (const ulonglong2*)(qkvU + tt * 96 + 32 + h * 4);
                    ulonglong2 k0 = kp[0], k1 = kp[1];
                    const ulonglong2* vp = (const ulonglong2*)(qkvU + tt * 96 + 64 + h * 4);
                    ulonglong2 v0 = vp[0], v1 = vp[1];
                    #pragma unroll
                    for (int r = 0; r < 4; r++) {
                        ull d2 = mul2_(q[r][0], k0.x);
                        d2 = fma2_(q[r][1], k0.y, d2);
                        d2 = fma2_(q[r][2], k1.x, d2);
                        d2 = fma2_(q[r][3], k1.y, d2);
                        float dl, dh; up2(d2, dl, dh);
                        float cbl, cbh; up2(cb2[r], cbl, cbh);
                        float p = ex2_(fmaf(dl + dh, KSCALE, u ? cbh : cbl));
                        sums[r] += p;
                        ull pp = pk2(p, p);
                        acc[r][0] = fma2_(pp, v0.x, acc[r][0]);
                        acc[r][1] = fma2_(pp, v0.y, acc[r][1]);
                        acc[r][2] = fma2_(pp, v1.x, acc[r][2]);
                        acc[r][3] = fma2_(pp, v1.y, acc[r][3]);
                    }
                }
            }
            #pragma unroll
            for (int r = 0; r < 4; r++) {
                float inv = 1.0f / sums[r];
                ull iv = pk2(inv, inv);
                float* aop = xb_ + (sl + 16 * r) * 65 + h * 8;
                #pragma unroll
                for (int d = 0; d < 4; d++) {
                    float lo, hi;
                    up2(mul2_(acc[r][d], iv), lo, hi);
                    aop[2 * d] = lo; aop[2 * d + 1] = hi;
                }
            }
        }
        hbar(half);

        // ---- phase 5: out-proj. rows ty+16ss, ull pairs {2tx,2tx+1}.
        //      weight = 1 LDS.128 per t. yT[e][s] (reuses qkv). ----
        {
            ulonglong2 acc[4];
            ulonglong2 bv = *(const ulonglong2*)(obU + 2 * tx);
            #pragma unroll
            for (int ss = 0; ss < 4; ss++) acc[ss] = bv;
            #pragma unroll 4
            for (int t = 0; t < 64; t++) {
                ulonglong2 w = *(const ulonglong2*)(owU + t * 32 + 2 * tx);
                #pragma unroll
                for (int ss = 0; ss < 4; ss++) {
                    float a = xb_[(ty + 16 * ss) * 65 + t];
                    ull ap = pk2(a, a);
                    acc[ss].x = fma2_(ap, w.x, acc[ss].x);
                    acc[ss].y = fma2_(ap, w.y, acc[ss].y);
                }
            }
            #pragma unroll
            for (int ss = 0; ss < 4; ss++) {
                int r = ty + 16 * ss;
                float lo, hi;
                up2(acc[ss].x, lo, hi);
                yT[(4 * tx) * 65 + r]     = lo;
                yT[(4 * tx + 1) * 65 + r] = hi;
                up2(acc[ss].y, lo, hi);
                yT[(4 * tx + 2) * 65 + r] = lo;
                yT[(4 * tx + 3) * 65 + r] = hi;
            }
        }
        hbar(half);

        // ---- phase 6: residual (reload x) + y, coalesced float4 stores ----
        float4* ob4 = (float4*)(gout + (size_t)b * 4096);
        for (int i4 = tidh; i4 < 1024; i4 += 256) {
            float4 xv = xb4[i4], pv = pos4[i4];
            int e = i4 >> 4, s0 = (i4 & 15) * 4;
            const float* yp = yT + e * 65 + s0;
            float4 o;
            o.x = xv.x + pv.x + yp[0];
            o.y = xv.y + pv.y + yp[1];
            o.z = xv.z + pv.z + yp[2];
            o.w = xv.w + pv.w + yp[3];
            ob4[i4] = o;
        }
    }
}

extern "C" void kernel_launch(void* const* d_in, const int* in_sizes, int n_in,
                              void* d_out, int out_size)
{
    (void)in_sizes; (void)n_in; (void)out_size;
    cudaFuncSetAttribute(chess_attn_kernel,
                         cudaFuncAttributeMaxDynamicSharedMemorySize, SMEM_BYTES);
    hx_reset_counter<<<1, 1>>>();
    chess_attn_kernel<<<152, TPB, SMEM_BYTES>>>(
        (const float*)d_in[0], (const float*)d_in[1], (const float*)d_in[2],
        (const float*)d_in[3], (const float*)d_in[4], (const float*)d_in[5],
        (const float*)d_in[6], (const float*)d_in[7], (const float*)d_in[8],
        (float*)d_out);
}

// round 8
// speedup vs baseline: 1.4536x; 1.0774x over previous
#include <cuda_runtime.h>

// ChessMultiStageAttention — persistent CTA, two independent 256-thread
// pipelines (named barriers), f32x2 math.
// Round 8: R7 design (8-warp lane-split attention, prefetched residual,
// STS.128 ao) with pos_embed evicted from smem (L2-resident) to fit the
// 227KB dynamic smem cap. Total smem = 217,120 B.

#define TPB 512
#define NBATCH 4096
typedef unsigned long long ull;

__device__ int g_next_batch;
__global__ void hx_reset_counter() { g_next_batch = 0; }

__device__ __forceinline__ ull pk2(float x, float y) {
    ull r; asm("mov.b64 %0,{%1,%2};" : "=l"(r) : "f"(x), "f"(y)); return r;
}
__device__ __forceinline__ void up2(ull p, float& x, float& y) {
    asm("mov.b64 {%0,%1},%2;" : "=f"(x), "=f"(y) : "l"(p));
}
__device__ __forceinline__ ull fma2_(ull a, ull b, ull c) {
    ull d; asm("fma.rn.f32x2 %0,%1,%2,%3;" : "=l"(d) : "l"(a), "l"(b), "l"(c)); return d;
}
__device__ __forceinline__ ull mul2_(ull a, ull b) {
    ull d; asm("mul.rn.f32x2 %0,%1,%2;" : "=l"(d) : "l"(a), "l"(b)); return d;
}
__device__ __forceinline__ float ex2_(float x) {
    float r; asm("ex2.approx.f32 %0,%1;" : "=f"(r) : "f"(x)); return r;
}
__device__ __forceinline__ void hbar(int half) {
    asm volatile("bar.sync %0, 256;" :: "r"(1 + half) : "memory");
}

#define LOG2E 1.4426950408889634f
#define KSCALE (0.35355339059327373f * 1.4426950408889634f)

// smem offsets in floats (total 54280 fl = 217,120 B < 232,448 B cap)
#define OFF_W2F  0                    // 12288  w2f[e][j] = qkv_w[j][e]
#define OFF_OWF  12288                // 4096   owf[t][e] = out_w[e][t]
#define OFF_CB   16384                // 4224   cb[s*66+t] * log2e
#define OFF_QB   20608                // 192
#define OFF_OB   20800                // 64
#define OFF_G    20864                // 64
#define OFF_BT   20928                // 64
#define OFF_BB   20992                // 8
#define OFF_QKV0 21000                // 12288 per half (ull stride 96)
#define OFF_QKV1 33288
#define OFF_XB0  45576                // 4352 per half (xn [e][s] str65 / ao [s][e] str68)
#define OFF_XB1  49928
#define SMEM_FLOATS 54280
#define SMEM_BYTES  (SMEM_FLOATS * 4)

extern "C" __global__ void __launch_bounds__(TPB)
chess_attn_kernel(const float* __restrict__ gx,
                  const float* __restrict__ gpos,
                  const float* __restrict__ ggamma,
                  const float* __restrict__ gbeta,
                  const float* __restrict__ gqkvw,
                  const float* __restrict__ gqkvb,
                  const float* __restrict__ goutw,
                  const float* __restrict__ goutb,
                  const float* __restrict__ gcb,
                  float* __restrict__ gout)
{
    extern __shared__ float sm[];
    float* sm_w2f = sm + OFF_W2F;
    float* sm_owf = sm + OFF_OWF;
    float* sm_cb  = sm + OFF_CB;
    float* sm_qb  = sm + OFF_QB;
    float* sm_ob  = sm + OFF_OB;
    float* sm_g   = sm + OFF_G;
    float* sm_bt  = sm + OFF_BT;
    int*   sm_bb  = (int*)(sm + OFF_BB);

    const int tid  = threadIdx.x;
    const int lane = tid & 31;
    const int warp = tid >> 5;
    const int half = warp >> 3;
    const int tidh = tid & 255;
    const int wh   = warp & 7;
    const int tx   = tidh & 15;
    const int ty   = tidh >> 4;          // 0..15

    float* xb_  = sm + (half ? OFF_XB1 : OFF_XB0);   // xn [e][s] str65; ao [s][e] str68
    float* qkvf = sm + (half ? OFF_QKV1 : OFF_QKV0);
    ull*   qkvU = (ull*)qkvf;                        // row stride 96 ull
    float* yT   = qkvf;                              // [e][s] stride 65 (reuses qkv)
    ull*   w2U  = (ull*)sm_w2f;
    ull*   owU  = (ull*)sm_owf;
    ull*   qbU  = (ull*)sm_qb;
    ull*   obU  = (ull*)sm_ob;

    // ---- stage constants ----
    for (int i = tid; i < 192 * 64; i += TPB) {
        int j = i >> 6, e = i & 63;
        sm_w2f[e * 192 + j] = gqkvw[i];
    }
    for (int i = tid; i < 64 * 64; i += TPB) {
        int e = i >> 6, t = i & 63;
        sm_owf[t * 64 + e] = goutw[i];
    }
    for (int i = tid; i < 64 * 64; i += TPB) {
        int s = i >> 6, t = i & 63;
        sm_cb[s * 66 + t] = gcb[i] * LOG2E;
    }
    if (tid < 192) sm_qb[tid] = gqkvb[tid];
    if (tid < 64) { sm_ob[tid] = goutb[tid]; sm_g[tid] = ggamma[tid]; sm_bt[tid] = gbeta[tid]; }
    __syncthreads();

    const float4* pos4 = (const float4*)gpos;   // 16KB, L2-resident

    while (true) {
        hbar(half);
        if (tidh == 0) sm_bb[half] = atomicAdd(&g_next_batch, 1);
        hbar(half);
        int b = sm_bb[half];
        if (b >= NBATCH) break;
        const float4* xb4 = (const float4*)(gx + (size_t)b * 4096);

        // ---- phase 1: x + pos into xb_ [e][s] (stride 65) ----
        float4 xreg[4], preg[4];
        #pragma unroll
        for (int it = 0; it < 4; it++) {
            int i4 = tidh + 256 * it;
            float4 xv = xb4[i4], pv = pos4[i4];
            int e = i4 >> 4, s0 = (i4 & 15) * 4;
            float* p = xb_ + e * 65 + s0;
            p[0] = xv.x + pv.x;
            p[1] = xv.y + pv.y;
            p[2] = xv.z + pv.z;
            p[3] = xv.w + pv.w;
        }
        hbar(half);

        // ---- phase 2: LayerNorm in-place over e (warp per column pair) ----
        #pragma unroll
        for (int k = 0; k < 4; k++) {
            int s0 = wh * 8 + 2 * k, s1 = s0 + 1;
            float a0 = xb_[lane * 65 + s0];
            float a1 = xb_[(lane + 32) * 65 + s0];
            float b0 = xb_[lane * 65 + s1];
            float b1 = xb_[(lane + 32) * 65 + s1];
            float sa = a0 + a1, qa = a0 * a0 + a1 * a1;
            float sb = b0 + b1, qb2 = b0 * b0 + b1 * b1;
            #pragma unroll
            for (int off = 16; off; off >>= 1) {
                sa  += __shfl_xor_sync(0xffffffffu, sa,  off);
                qa  += __shfl_xor_sync(0xffffffffu, qa,  off);
                sb  += __shfl_xor_sync(0xffffffffu, sb,  off);
                qb2 += __shfl_xor_sync(0xffffffffu, qb2, off);
            }
            float muA = sa * (1.0f / 64.0f);
            float rsA = rsqrtf(qa * (1.0f / 64.0f) - muA * muA + 1e-5f);
            float muB = sb * (1.0f / 64.0f);
            float rsB = rsqrtf(qb2 * (1.0f / 64.0f) - muB * muB + 1e-5f);
            float g0 = sm_g[lane], g1 = sm_g[lane + 32];
            float t0 = sm_bt[lane], t1 = sm_bt[lane + 32];
            xb_[lane * 65 + s0]        = (a0 - muA) * rsA * g0 + t0;
            xb_[(lane + 32) * 65 + s0] = (a1 - muA) * rsA * g1 + t1;
            xb_[lane * 65 + s1]        = (b0 - muB) * rsB * g0 + t0;
            xb_[(lane + 32) * 65 + s1] = (b1 - muB) * rsB * g1 + t1;
        }
        hbar(half);

        // ---- phase 3: QKV GEMM. thread (tx,ty): rows ty+16ss,
        //      ull pairs {2tx+32m, 2tx+32m+1} -> LDS.128 weights/stores ----
        {
            ulonglong2 acc[4][3];
            #pragma unroll
            for (int m = 0; m < 3; m++) {
                ulonglong2 bv = *(const ulonglong2*)(qbU + 2 * tx + 32 * m);
                #pragma unroll
                for (int ss = 0; ss < 4; ss++) acc[ss][m] = bv;
            }
            #pragma unroll 4
            for (int e = 0; e < 64; e++) {
                ull ap[4];
                #pragma unroll
                for (int ss = 0; ss < 4; ss++) {
                    float a = xb_[e * 65 + ty + 16 * ss];
                    ap[ss] = pk2(a, a);
                }
                ulonglong2 w[3];
                #pragma unroll
                for (int m = 0; m < 3; m++)
                    w[m] = *(const ulonglong2*)(w2U + e * 96 + 2 * tx + 32 * m);
                #pragma unroll
                for (int ss = 0; ss < 4; ss++)
                    #pragma unroll
                    for (int m = 0; m < 3; m++) {
                        acc[ss][m].x = fma2_(ap[ss], w[m].x, acc[ss][m].x);
                        acc[ss][m].y = fma2_(ap[ss], w[m].y, acc[ss][m].y);
                    }
            }
            #pragma unroll
            for (int ss = 0; ss < 4; ss++)
                #pragma unroll
                for (int m = 0; m < 3; m++)
                    *(ulonglong2*)(qkvU + (ty + 16 * ss) * 96 + 2 * tx + 32 * m) = acc[ss][m];
        }
        hbar(half);

        // ---- phase 4: attention on ALL 8 warps. warp wh: head-pair (wh&3),
        //      row-half (wh>>2); lanes 0-15 head A, 16-31 head B, 2 rows/lane ----
        {
            const int h  = 2 * (wh & 3) + (lane >> 4);
            const int rb = (wh >> 2) * 2;          // row-block: r in {rb, rb+1}
            const int sl = lane & 15;
            ull q[2][4];
            #pragma unroll
            for (int r = 0; r < 2; r++) {
                const ulonglong2* qp =
                    (const ulonglong2*)(qkvU + (sl + 16 * (rb + r)) * 96 + h * 4);
                ulonglong2 qa = qp[0], qb_ = qp[1];
                q[r][0] = qa.x; q[r][1] = qa.y; q[r][2] = qb_.x; q[r][3] = qb_.y;
            }
            ull acc[2][4];
            #pragma unroll
            for (int r = 0; r < 2; r++)
                #pragma unroll
                for (int d = 0; d < 4; d++) acc[r][d] = 0;
            float sums[2] = {0.f, 0.f};
            #pragma unroll 2
            for (int t = 0; t < 64; t += 2) {
                ull cb2[2];
                #pragma unroll
                for (int r = 0; r < 2; r++)
                    cb2[r] = *(const ull*)(sm_cb + (sl + 16 * (rb + r)) * 66 + t);
                #pragma unroll
                for (int u = 0; u < 2; u++) {
                    int tt = t + u;
                    const ulonglong2* kp = (const ulonglong2*)(qkvU + tt * 96 + 32 + h * 4);
                    ulonglong2 k0 = kp[0], k1 = kp[1];
                    const ulonglong2* vp = (const ulonglong2*)(qkvU + tt * 96 + 64 + h * 4);
                    ulonglong2 v0 = vp[0], v1 = vp[1];
                    #pragma unroll
                    for (int r = 0; r < 2; r++) {
                        ull d2 = mul2_(q[r][0], k0.x);
                        d2 = fma2_(q[r][1], k0.y, d2);
                        d2 = fma2_(q[r][2], k1.x, d2);
                        d2 = fma2_(q[r][3], k1.y, d2);
                        float dl, dh; up2(d2, dl, dh);
                        float cbl, cbh; up2(cb2[r], cbl, cbh);
                        float p = ex2_(fmaf(dl + dh, KSCALE, u ? cbh : cbl));
                        sums[r] += p;
                        ull pp = pk2(p, p);
                        acc[r][0] = fma2_(pp, v0.x, acc[r][0]);
                        acc[r][1] = fma2_(pp, v0.y, acc[r][1]);
                        acc[r][2] = fma2_(pp, v1.x, acc[r][2]);
                        acc[r][3] = fma2_(pp, v1.y, acc[r][3]);
                    }
                }
            }
            // ao -> xb_ as [s][e] stride 68, 16B-aligned STS.128
            #pragma unroll
            for (int r = 0; r < 2; r++) {
                float inv = 1.0f / sums[r];
                ull iv = pk2(inv, inv);
                float4* aop = (float4*)(xb_ + (sl + 16 * (rb + r)) * 68 + h * 8);
                float4 o0, o1;
                up2(mul2_(acc[r][0], iv), o0.x, o0.y);
                up2(mul2_(acc[r][1], iv), o0.z, o0.w);
                up2(mul2_(acc[r][2], iv), o1.x, o1.y);
                up2(mul2_(acc[r][3], iv), o1.z, o1.w);
                aop[0] = o0; aop[1] = o1;
            }
        }
        hbar(half);

        // ---- early-issue residual + pos LDGs for phase 6 ----
        #pragma unroll
        for (int it = 0; it < 4; it++) {
            xreg[it] = xb4[tidh + 256 * it];
            preg[it] = pos4[tidh + 256 * it];
        }

        // ---- phase 5: out-proj. rows ty+16ss, ull pairs {2tx,2tx+1};
        //      activations via LDS.128 t-blocks (ao rows contiguous). ----
        {
            ulonglong2 acc[4];
            ulonglong2 bv = *(const ulonglong2*)(obU + 2 * tx);
            #pragma unroll
            for (int ss = 0; ss < 4; ss++) acc[ss] = bv;
            #pragma unroll 2
            for (int t0 = 0; t0 < 64; t0 += 4) {
                float4 av[4];
                #pragma unroll
                for (int ss = 0; ss < 4; ss++)
                    av[ss] = *(const float4*)(xb_ + (ty + 16 * ss) * 68 + t0);
                #pragma unroll
                for (int k = 0; k < 4; k++) {
                    int t = t0 + k;
                    ulonglong2 w = *(const ulonglong2*)(owU + t * 32 + 2 * tx);
                    #pragma unroll
                    for (int ss = 0; ss < 4; ss++) {
                        float a = (k == 0) ? av[ss].x : (k == 1) ? av[ss].y
                                : (k == 2) ? av[ss].z : av[ss].w;
                        ull ap = pk2(a, a);
                        acc[ss].x = fma2_(ap, w.x, acc[ss].x);
                        acc[ss].y = fma2_(ap, w.y, acc[ss].y);
                    }
                }
            }
            #pragma unroll
            for (int ss = 0; ss < 4; ss++) {
                int r = ty + 16 * ss;
                float lo, hi;
                up2(acc[ss].x, lo, hi);
                yT[(4 * tx) * 65 + r]     = lo;
                yT[(4 * tx + 1) * 65 + r] = hi;
                up2(acc[ss].y, lo, hi);
                yT[(4 * tx + 2) * 65 + r] = lo;
                yT[(4 * tx + 3) * 65 + r] = hi;
            }
        }
        hbar(half);

        // ---- phase 6: residual (prefetched x+pos) + y, float4 stores ----
        float4* ob4 = (float4*)(gout + (size_t)b * 4096);
        #pragma unroll
        for (int it = 0; it < 4; it++) {
            int i4 = tidh + 256 * it;
            float4 xv = xreg[it], pv = preg[it];
            int e = i4 >> 4, s0 = (i4 & 15) * 4;
            const float* yp = yT + e * 65 + s0;
            float4 o;
            o.x = xv.x + pv.x + yp[0];
            o.y = xv.y + pv.y + yp[1];
            o.z = xv.z + pv.z + yp[2];
            o.w = xv.w + pv.w + yp[3];
            ob4[i4] = o;
        }
    }
}

extern "C" void kernel_launch(void* const* d_in, const int* in_sizes, int n_in,
                              void* d_out, int out_size)
{
    (void)in_sizes; (void)n_in; (void)out_size;
    cudaFuncSetAttribute(chess_attn_kernel,
                         cudaFuncAttributeMaxDynamicSharedMemorySize, SMEM_BYTES);
    hx_reset_counter<<<1, 1>>>();
    chess_attn_kernel<<<152, TPB, SMEM_BYTES>>>(
        (const float*)d_in[0], (const float*)d_in[1], (const float*)d_in[2],
        (const float*)d_in[3], (const float*)d_in[4], (const float*)d_in[5],
        (const float*)d_in[6], (const float*)d_in[7], (const float*)d_in[8],
        (float*)d_out);
}

// round 9
// speedup vs baseline: 1.4547x; 1.0007x over previous
#include <cuda_runtime.h>

// ChessMultiStageAttention — persistent CTA, two independent 256-thread
// pipelines (named barriers), f32x2 math.
// Round 8: R7 design (8-warp lane-split attention, prefetched residual,
// STS.128 ao) with pos_embed evicted from smem (L2-resident) to fit the
// 227KB dynamic smem cap. Total smem = 217,120 B.

#define TPB 512
#define NBATCH 4096
typedef unsigned long long ull;

__device__ int g_next_batch;
__global__ void hx_reset_counter() { g_next_batch = 0; }

__device__ __forceinline__ ull pk2(float x, float y) {
    ull r; asm("mov.b64 %0,{%1,%2};" : "=l"(r) : "f"(x), "f"(y)); return r;
}
__device__ __forceinline__ void up2(ull p, float& x, float& y) {
    asm("mov.b64 {%0,%1},%2;" : "=f"(x), "=f"(y) : "l"(p));
}
__device__ __forceinline__ ull fma2_(ull a, ull b, ull c) {
    ull d; asm("fma.rn.f32x2 %0,%1,%2,%3;" : "=l"(d) : "l"(a), "l"(b), "l"(c)); return d;
}
__device__ __forceinline__ ull mul2_(ull a, ull b) {
    ull d; asm("mul.rn.f32x2 %0,%1,%2;" : "=l"(d) : "l"(a), "l"(b)); return d;
}
__device__ __forceinline__ float ex2_(float x) {
    float r; asm("ex2.approx.f32 %0,%1;" : "=f"(r) : "f"(x)); return r;
}
__device__ __forceinline__ void hbar(int half) {
    asm volatile("bar.sync %0, 256;" :: "r"(1 + half) : "memory");
}

#define LOG2E 1.4426950408889634f
#define KSCALE (0.35355339059327373f * 1.4426950408889634f)

// smem offsets in floats (total 54280 fl = 217,120 B < 232,448 B cap)
#define OFF_W2F  0                    // 12288  w2f[e][j] = qkv_w[j][e]
#define OFF_OWF  12288                // 4096   owf[t][e] = out_w[e][t]
#define OFF_CB   16384                // 4224   cb[s*66+t] * log2e
#define OFF_QB   20608                // 192
#define OFF_OB   20800                // 64
#define OFF_G    20864                // 64
#define OFF_BT   20928                // 64
#define OFF_BB   20992                // 8
#define OFF_QKV0 21000                // 12288 per half (ull stride 96)
#define OFF_QKV1 33288
#define OFF_XB0  45576                // 4352 per half (xn [e][s] str65 / ao [s][e] str68)
#define OFF_XB1  49928
#define SMEM_FLOATS 54280
#define SMEM_BYTES  (SMEM_FLOATS * 4)

extern "C" __global__ void __launch_bounds__(TPB)
chess_attn_kernel(const float* __restrict__ gx,
                  const float* __restrict__ gpos,
                  const float* __restrict__ ggamma,
                  const float* __restrict__ gbeta,
                  const float* __restrict__ gqkvw,
                  const float* __restrict__ gqkvb,
                  const float* __restrict__ goutw,
                  const float* __restrict__ goutb,
                  const float* __restrict__ gcb,
                  float* __restrict__ gout)
{
    extern __shared__ float sm[];
    float* sm_w2f = sm + OFF_W2F;
    float* sm_owf = sm + OFF_OWF;
    float* sm_cb  = sm + OFF_CB;
    float* sm_qb  = sm + OFF_QB;
    float* sm_ob  = sm + OFF_OB;
    float* sm_g   = sm + OFF_G;
    float* sm_bt  = sm + OFF_BT;
    int*   sm_bb  = (int*)(sm + OFF_BB);

    const int tid  = threadIdx.x;
    const int lane = tid & 31;
    const int warp = tid >> 5;
    const int half = warp >> 3;
    const int tidh = tid & 255;
    const int wh   = warp & 7;
    const int tx   = tidh & 15;
    const int ty   = tidh >> 4;          // 0..15

    float* xb_  = sm + (half ? OFF_XB1 : OFF_XB0);   // xn [e][s] str65; ao [s][e] str68
    float* qkvf = sm + (half ? OFF_QKV1 : OFF_QKV0);
    ull*   qkvU = (ull*)qkvf;                        // row stride 96 ull
    float* yT   = qkvf;                              // [e][s] stride 65 (reuses qkv)
    ull*   w2U  = (ull*)sm_w2f;
    ull*   owU  = (ull*)sm_owf;
    ull*   qbU  = (ull*)sm_qb;
    ull*   obU  = (ull*)sm_ob;

    // ---- stage constants ----
    for (int i = tid; i < 192 * 64; i += TPB) {
        int j = i >> 6, e = i & 63;
        sm_w2f[e * 192 + j] = gqkvw[i];
    }
    for (int i = tid; i < 64 * 64; i += TPB) {
        int e = i >> 6, t = i & 63;
        sm_owf[t * 64 + e] = goutw[i];
    }
    for (int i = tid; i < 64 * 64; i += TPB) {
        int s = i >> 6, t = i & 63;
        sm_cb[s * 66 + t] = gcb[i] * LOG2E;
    }
    if (tid < 192) sm_qb[tid] = gqkvb[tid];
    if (tid < 64) { sm_ob[tid] = goutb[tid]; sm_g[tid] = ggamma[tid]; sm_bt[tid] = gbeta[tid]; }
    __syncthreads();

    const float4* pos4 = (const float4*)gpos;   // 16KB, L2-resident

    while (true) {
        hbar(half);
        if (tidh == 0) sm_bb[half] = atomicAdd(&g_next_batch, 1);
        hbar(half);
        int b = sm_bb[half];
        if (b >= NBATCH) break;
        const float4* xb4 = (const float4*)(gx + (size_t)b * 4096);

        // ---- phase 1: x + pos into xb_ [e][s] (stride 65) ----
        float4 xreg[4], preg[4];
        #pragma unroll
        for (int it = 0; it < 4; it++) {
            int i4 = tidh + 256 * it;
            float4 xv = xb4[i4], pv = pos4[i4];
            int e = i4 >> 4, s0 = (i4 & 15) * 4;
            float* p = xb_ + e * 65 + s0;
            p[0] = xv.x + pv.x;
            p[1] = xv.y + pv.y;
            p[2] = xv.z + pv.z;
            p[3] = xv.w + pv.w;
        }
        hbar(half);

        // ---- phase 2: LayerNorm in-place over e (warp per column pair) ----
        #pragma unroll
        for (int k = 0; k < 4; k++) {
            int s0 = wh * 8 + 2 * k, s1 = s0 + 1;
            float a0 = xb_[lane * 65 + s0];
            float a1 = xb_[(lane + 32) * 65 + s0];
            float b0 = xb_[lane * 65 + s1];
            float b1 = xb_[(lane + 32) * 65 + s1];
            float sa = a0 + a1, qa = a0 * a0 + a1 * a1;
            float sb = b0 + b1, qb2 = b0 * b0 + b1 * b1;
            #pragma unroll
            for (int off = 16; off; off >>= 1) {
                sa  += __shfl_xor_sync(0xffffffffu, sa,  off);
                qa  += __shfl_xor_sync(0xffffffffu, qa,  off);
                sb  += __shfl_xor_sync(0xffffffffu, sb,  off);
                qb2 += __shfl_xor_sync(0xffffffffu, qb2, off);
            }
            float muA = sa * (1.0f / 64.0f);
            float rsA = rsqrtf(qa * (1.0f / 64.0f) - muA * muA + 1e-5f);
            float muB = sb * (1.0f / 64.0f);
            float rsB = rsqrtf(qb2 * (1.0f / 64.0f) - muB * muB + 1e-5f);
            float g0 = sm_g[lane], g1 = sm_g[lane + 32];
            float t0 = sm_bt[lane], t1 = sm_bt[lane + 32];
            xb_[lane * 65 + s0]        = (a0 - muA) * rsA * g0 + t0;
            xb_[(lane + 32) * 65 + s0] = (a1 - muA) * rsA * g1 + t1;
            xb_[lane * 65 + s1]        = (b0 - muB) * rsB * g0 + t0;
            xb_[(lane + 32) * 65 + s1] = (b1 - muB) * rsB * g1 + t1;
        }
        hbar(half);

        // ---- phase 3: QKV GEMM. thread (tx,ty): rows ty+16ss,
        //      ull pairs {2tx+32m, 2tx+32m+1} -> LDS.128 weights/stores ----
        {
            ulonglong2 acc[4][3];
            #pragma unroll
            for (int m = 0; m < 3; m++) {
                ulonglong2 bv = *(const ulonglong2*)(qbU + 2 * tx + 32 * m);
                #pragma unroll
                for (int ss = 0; ss < 4; ss++) acc[ss][m] = bv;
            }
            #pragma unroll 4
            for (int e = 0; e < 64; e++) {
                ull ap[4];
                #pragma unroll
                for (int ss = 0; ss < 4; ss++) {
                    float a = xb_[e * 65 + ty + 16 * ss];
                    ap[ss] = pk2(a, a);
                }
                ulonglong2 w[3];
                #pragma unroll
                for (int m = 0; m < 3; m++)
                    w[m] = *(const ulonglong2*)(w2U + e * 96 + 2 * tx + 32 * m);
                #pragma unroll
                for (int ss = 0; ss < 4; ss++)
                    #pragma unroll
                    for (int m = 0; m < 3; m++) {
                        acc[ss][m].x = fma2_(ap[ss], w[m].x, acc[ss][m].x);
                        acc[ss][m].y = fma2_(ap[ss], w[m].y, acc[ss][m].y);
                    }
            }
            #pragma unroll
            for (int ss = 0; ss < 4; ss++)
                #pragma unroll
                for (int m = 0; m < 3; m++)
                    *(ulonglong2*)(qkvU + (ty + 16 * ss) * 96 + 2 * tx + 32 * m) = acc[ss][m];
        }
        hbar(half);

        // ---- phase 4: attention on ALL 8 warps. warp wh: head-pair (wh&3),
        //      row-half (wh>>2); lanes 0-15 head A, 16-31 head B, 2 rows/lane ----
        {
            const int h  = 2 * (wh & 3) + (lane >> 4);
            const int rb = (wh >> 2) * 2;          // row-block: r in {rb, rb+1}
            const int sl = lane & 15;
            ull q[2][4];
            #pragma unroll
            for (int r = 0; r < 2; r++) {
                const ulonglong2* qp =
                    (const ulonglong2*)(qkvU + (sl + 16 * (rb + r)) * 96 + h * 4);
                ulonglong2 qa = qp[0], qb_ = qp[1];
                q[r][0] = qa.x; q[r][1] = qa.y; q[r][2] = qb_.x; q[r][3] = qb_.y;
            }
            ull acc[2][4];
            #pragma unroll
            for (int r = 0; r < 2; r++)
                #pragma unroll
                for (int d = 0; d < 4; d++) acc[r][d] = 0;
            float sums[2] = {0.f, 0.f};
            #pragma unroll 2
            for (int t = 0; t < 64; t += 2) {
                ull cb2[2];
                #pragma unroll
                for (int r = 0; r < 2; r++)
                    cb2[r] = *(const ull*)(sm_cb + (sl + 16 * (rb + r)) * 66 + t);
                #pragma unroll
                for (int u = 0; u < 2; u++) {
                    int tt = t + u;
                    const ulonglong2* kp = (const ulonglong2*)(qkvU + tt * 96 + 32 + h * 4);
                    ulonglong2 k0 = kp[0], k1 = kp[1];
                    const ulonglong2* vp = (const ulonglong2*)(qkvU + tt * 96 + 64 + h * 4);
                    ulonglong2 v0 = vp[0], v1 = vp[1];
                    #pragma unroll
                    for (int r = 0; r < 2; r++) {
                        ull d2 = mul2_(q[r][0], k0.x);
                        d2 = fma2_(q[r][1], k0.y, d2);
                        d2 = fma2_(q[r][2], k1.x, d2);
                        d2 = fma2_(q[r][3], k1.y, d2);
                        float dl, dh; up2(d2, dl, dh);
                        float cbl, cbh; up2(cb2[r], cbl, cbh);
                        float p = ex2_(fmaf(dl + dh, KSCALE, u ? cbh : cbl));
                        sums[r] += p;
                        ull pp = pk2(p, p);
                        acc[r][0] = fma2_(pp, v0.x, acc[r][0]);
                        acc[r][1] = fma2_(pp, v0.y, acc[r][1]);
                        acc[r][2] = fma2_(pp, v1.x, acc[r][2]);
                        acc[r][3] = fma2_(pp, v1.y, acc[r][3]);
                    }
                }
            }
            // ao -> xb_ as [s][e] stride 68, 16B-aligned STS.128
            #pragma unroll
            for (int r = 0; r < 2; r++) {
                float inv = 1.0f / sums[r];
                ull iv = pk2(inv, inv);
                float4* aop = (float4*)(xb_ + (sl + 16 * (rb + r)) * 68 + h * 8);
                float4 o0, o1;
                up2(mul2_(acc[r][0], iv), o0.x, o0.y);
                up2(mul2_(acc[r][1], iv), o0.z, o0.w);
                up2(mul2_(acc[r][2], iv), o1.x, o1.y);
                up2(mul2_(acc[r][3], iv), o1.z, o1.w);
                aop[0] = o0; aop[1] = o1;
            }
        }
        hbar(half);

        // ---- early-issue residual + pos LDGs for phase 6 ----
        #pragma unroll
        for (int it = 0; it < 4; it++) {
            xreg[it] = xb4[tidh + 256 * it];
            preg[it] = pos4[tidh + 256 * it];
        }

        // ---- phase 5: out-proj. rows ty+16ss, ull pairs {2tx,2tx+1};
        //      activations via LDS.128 t-blocks (ao rows contiguous). ----
        {
            ulonglong2 acc[4];
            ulonglong2 bv = *(const ulonglong2*)(obU + 2 * tx);
            #pragma unroll
            for (int ss = 0; ss < 4; ss++) acc[ss] = bv;
            #pragma unroll 2
            for (int t0 = 0; t0 < 64; t0 += 4) {
                float4 av[4];
                #pragma unroll
                for (int ss = 0; ss < 4; ss++)
                    av[ss] = *(const float4*)(xb_ + (ty + 16 * ss) * 68 + t0);
                #pragma unroll
                for (int k = 0; k < 4; k++) {
                    int t = t0 + k;
                    ulonglong2 w = *(const ulonglong2*)(owU + t * 32 + 2 * tx);
                    #pragma unroll
                    for (int ss = 0; ss < 4; ss++) {
                        float a = (k == 0) ? av[ss].x : (k == 1) ? av[ss].y
                                : (k == 2) ? av[ss].z : av[ss].w;
                        ull ap = pk2(a, a);
                        acc[ss].x = fma2_(ap, w.x, acc[ss].x);
                        acc[ss].y = fma2_(ap, w.y, acc[ss].y);
                    }
                }
            }
            #pragma unroll
            for (int ss = 0; ss < 4; ss++) {
                int r = ty + 16 * ss;
                float lo, hi;
                up2(acc[ss].x, lo, hi);
                yT[(4 * tx) * 65 + r]     = lo;
                yT[(4 * tx + 1) * 65 + r] = hi;
                up2(acc[ss].y, lo, hi);
                yT[(4 * tx + 2) * 65 + r] = lo;
                yT[(4 * tx + 3) * 65 + r] = hi;
            }
        }
        hbar(half);

        // ---- phase 6: residual (prefetched x+pos) + y, float4 stores ----
        float4* ob4 = (float4*)(gout + (size_t)b * 4096);
        #pragma unroll
        for (int it = 0; it < 4; it++) {
            int i4 = tidh + 256 * it;
            float4 xv = xreg[it], pv = preg[it];
            int e = i4 >> 4, s0 = (i4 & 15) * 4;
            const float* yp = yT + e * 65 + s0;
            float4 o;
            o.x = xv.x + pv.x + yp[0];
            o.y = xv.y + pv.y + yp[1];
            o.z = xv.z + pv.z + yp[2];
            o.w = xv.w + pv.w + yp[3];
            ob4[i4] = o;
        }
    }
}

extern "C" void kernel_launch(void* const* d_in, const int* in_sizes, int n_in,
                              void* d_out, int out_size)
{
    (void)in_sizes; (void)n_in; (void)out_size;
    cudaFuncSetAttribute(chess_attn_kernel,
                         cudaFuncAttributeMaxDynamicSharedMemorySize, SMEM_BYTES);
    hx_reset_counter<<<1, 1>>>();
    chess_attn_kernel<<<152, TPB, SMEM_BYTES>>>(
        (const float*)d_in[0], (const float*)d_in[1], (const float*)d_in[2],
        (const float*)d_in[3], (const float*)d_in[4], (const float*)d_in[5],
        (const float*)d_in[6], (const float*)d_in[7], (const float*)d_in[8],
        (float*)d_out);
}

// round 13
// speedup vs baseline: 1.9686x; 1.3533x over previous
#include <cuda_runtime.h>

// Round 11: GEMMs on legacy tensor cores (mma.sync m16n8k16 bf16, hi/lo
// 3-pass split, fp32 accum) + ldmatrix; attention/LN stay scalar f32x2.
// Two independent 256-thread half-pipelines as in R8.

#define TPB 512
#define NBATCH 4096
typedef unsigned long long ull;
typedef unsigned int u32;

__device__ int g_next_batch;
__global__ void hx_reset_counter() { g_next_batch = 0; }

__device__ __forceinline__ ull pk2(float x, float y) {
    ull r; asm("mov.b64 %0,{%1,%2};" : "=l"(r) : "f"(x), "f"(y)); return r;
}
__device__ __forceinline__ void up2(ull p, float& x, float& y) {
    asm("mov.b64 {%0,%1},%2;" : "=f"(x), "=f"(y) : "l"(p));
}
__device__ __forceinline__ ull fma2_(ull a, ull b, ull c) {
    ull d; asm("fma.rn.f32x2 %0,%1,%2,%3;" : "=l"(d) : "l"(a), "l"(b), "l"(c)); return d;
}
__device__ __forceinline__ ull mul2_(ull a, ull b) {
    ull d; asm("mul.rn.f32x2 %0,%1,%2;" : "=l"(d) : "l"(a), "l"(b)); return d;
}
__device__ __forceinline__ float ex2_(float x) {
    float r; asm("ex2.approx.f32 %0,%1;" : "=f"(r) : "f"(x)); return r;
}
__device__ __forceinline__ void hbar(int half) {
    asm volatile("bar.sync %0, 256;" :: "r"(1 + half) : "memory");
}
__device__ __forceinline__ u32 s2u(const void* p) {
    u32 a; asm("{ .reg .u64 t; cvta.to.shared.u64 t, %1; cvt.u32.u64 %0, t; }"
               : "=r"(a) : "l"(p));
    return a;
}
// packed bf16x2: lower 16 bits = first arg, upper = second
__device__ __forceinline__ u32 bf2(float lo, float hi) {
    u32 r; asm("cvt.rn.bf16x2.f32 %0, %1, %2;" : "=r"(r) : "f"(hi), "f"(lo)); return r;
}
__device__ __forceinline__ float bflo(u32 p) { return __uint_as_float(p << 16); }
__device__ __forceinline__ float bfhi(u32 p) { return __uint_as_float(p & 0xFFFF0000u); }
__device__ __forceinline__ void ldsm4(u32* r, u32 a) {
    asm volatile("ldmatrix.sync.aligned.m8n8.x4.shared.b16 {%0,%1,%2,%3}, [%4];"
        : "=r"(r[0]), "=r"(r[1]), "=r"(r[2]), "=r"(r[3]) : "r"(a));
}
__device__ __forceinline__ void ldsm2(u32* r, u32 a) {
    asm volatile("ldmatrix.sync.aligned.m8n8.x2.shared.b16 {%0,%1}, [%2];"
        : "=r"(r[0]), "=r"(r[1]) : "r"(a));
}
__device__ __forceinline__ void mmabf(float* c, const u32* a, const u32* b) {
    asm volatile("mma.sync.aligned.m16n8k16.row.col.f32.bf16.bf16.f32 "
        "{%0,%1,%2,%3},{%4,%5,%6,%7},{%8,%9},{%0,%1,%2,%3};"
        : "+f"(c[0]), "+f"(c[1]), "+f"(c[2]), "+f"(c[3])
        : "r"(a[0]), "r"(a[1]), "r"(a[2]), "r"(a[3]), "r"(b[0]), "r"(b[1]));
}

#define LOG2E  1.4426950408889634f
#define KSCALE (0.35355339059327373f * 1.4426950408889634f)
#define SWZ(b) ((b) ^ (((b) >> 3) & 0x70))

// smem offsets (floats); b16 tiles are [rows][64 b16] = 128B rows, SW128
#define OFF_BQH 0        // 6144  qkv_w hi  [192][64]
#define OFF_BQL 6144
#define OFF_BOH 12288    // 2048  out_w hi  [64][64]
#define OFF_BOL 14336
#define OFF_AH0 16384    // 2048 per tile: A hi/lo per half [64][64]
#define OFF_AL0 18432
#define OFF_AH1 20480
#define OFF_AL1 22528
#define OFF_Q0  24576    // 12544 per half: xstage(s65)/qkv f32(ull s98)/yT(s65)
#define OFF_Q1  37120
#define OFF_CB  49664    // 4224  chess bias * log2e, stride 66
#define OFF_QB  53888    // 192
#define OFF_OB  54080    // 64
#define OFF_G   54144    // 64
#define OFF_BT  54208    // 64
#define OFF_BB  54272    // 8
#define SMEM_FLOATS 54280
#define SMEM_BYTES  (SMEM_FLOATS * 4)   // 217,120 B

__device__ __forceinline__ void stA(char* AH, char* AL, int row, int e, float v) {
    u32 hp = bf2(v, 0.f);
    u32 lp = bf2(v - bflo(hp), 0.f);
    u32 b = SWZ((u32)(row * 128 + e * 2));
    *(unsigned short*)(AH + b) = (unsigned short)hp;
    *(unsigned short*)(AL + b) = (unsigned short)lp;
}

extern "C" __global__ void __launch_bounds__(TPB)
chess_attn_kernel(const float* __restrict__ gx,
                  const float* __restrict__ gpos,
                  const float* __restrict__ ggamma,
                  const float* __restrict__ gbeta,
                  const float* __restrict__ gqkvw,
                  const float* __restrict__ gqkvb,
                  const float* __restrict__ goutw,
                  const float* __restrict__ goutb,
                  const float* __restrict__ gcb,
                  float* __restrict__ gout)
{
    extern __shared__ float sm[];
    float* sm_cb = sm + OFF_CB;
    float* sm_qb = sm + OFF_QB;
    float* sm_ob = sm + OFF_OB;
    float* sm_g  = sm + OFF_G;
    float* sm_bt = sm + OFF_BT;
    int*   sm_bb = (int*)(sm + OFF_BB);

    const int tid  = threadIdx.x;
    const int lane = tid & 31;
    const int warp = tid >> 5;
    const int half = warp >> 3;
    const int tidh = tid & 255;
    const int wh   = warp & 7;
    const u32 sb   = s2u(sm);

    float* qkvf = sm + (half ? OFF_Q1 : OFF_Q0);
    ull*   qU   = (ull*)qkvf;                  // f32 qkv, row stride 98 ull
    float* xst  = qkvf;                        // LN staging [e][s] stride 65
    float* yT   = qkvf;                        // y [e][s] stride 65
    char*  AHc  = (char*)(sm + (half ? OFF_AH1 : OFF_AH0));
    char*  ALc  = (char*)(sm + (half ? OFF_AL1 : OFF_AL0));
    const u32 AHa = sb + (half ? OFF_AH1 : OFF_AH0) * 4;
    const u32 ALa = sb + (half ? OFF_AL1 : OFF_AL0) * 4;
    const u32 BQH = sb + OFF_BQH * 4, BQL = sb + OFF_BQL * 4;
    const u32 BOH = sb + OFF_BOH * 4, BOL = sb + OFF_BOL * 4;

    // stage weights as bf16 hi/lo SW128 tiles
    char* BQHc = (char*)(sm + OFF_BQH);
    char* BQLc = (char*)(sm + OFF_BQL);
    char* BOHc = (char*)(sm + OFF_BOH);
    char* BOLc = (char*)(sm + OFF_BOL);
    for (int i = tid; i < 192 * 64; i += TPB) {
        int j = i >> 6, e = i & 63;
        float v = gqkvw[i];
        u32 hp = bf2(v, 0.f), lp = bf2(v - bflo(hp), 0.f);
        u32 b = SWZ((u32)(j * 128 + e * 2));
        *(unsigned short*)(BQHc + b) = (unsigned short)hp;
        *(unsigned short*)(BQLc + b) = (unsigned short)lp;
    }
    for (int i = tid; i < 64 * 64; i += TPB) {
        int e = i >> 6, t = i & 63;
        float v = goutw[i];
        u32 hp = bf2(v, 0.f), lp = bf2(v - bflo(hp), 0.f);
        u32 b = SWZ((u32)(e * 128 + t * 2));
        *(unsigned short*)(BOHc + b) = (unsigned short)hp;
        *(unsigned short*)(BOLc + b) = (unsigned short)lp;
    }
    for (int i = tid; i < 64 * 64; i += TPB) {
        int s = i >> 6, t = i & 63;
        sm_cb[s * 66 + t] = gcb[i] * LOG2E;
    }
    if (tid < 192) sm_qb[tid] = gqkvb[tid];
    if (tid < 64) { sm_ob[tid] = goutb[tid]; sm_g[tid] = ggamma[tid]; sm_bt[tid] = gbeta[tid]; }
    __syncthreads();

    const float4* pos4 = (const float4*)gpos;

    while (true) {
        hbar(half);
        if (tidh == 0) sm_bb[half] = atomicAdd(&g_next_batch, 1);
        hbar(half);
        int b = sm_bb[half];
        if (b >= NBATCH) break;
        const float4* xb4 = (const float4*)(gx + (size_t)b * 4096);

        // ---- P1: x + pos -> xst [e][s] stride 65 ----
        float4 xreg[4], preg[4];
        #pragma unroll
        for (int it = 0; it < 4; it++) {
            int i4 = tidh + 256 * it;
            float4 xv = xb4[i4], pv = pos4[i4];
            int e = i4 >> 4, s0 = (i4 & 15) * 4;
            float* p = xst + e * 65 + s0;
            p[0] = xv.x + pv.x; p[1] = xv.y + pv.y;
            p[2] = xv.z + pv.z; p[3] = xv.w + pv.w;
        }
        hbar(half);

        // ---- P2: LayerNorm -> A tiles (bf16 hi/lo) ----
        #pragma unroll
        for (int k = 0; k < 4; k++) {
            int s0 = wh * 8 + 2 * k, s1 = s0 + 1;
            float a0 = xst[lane * 65 + s0];
            float a1 = xst[(lane + 32) * 65 + s0];
            float b0 = xst[lane * 65 + s1];
            float b1 = xst[(lane + 32) * 65 + s1];
            float sa = a0 + a1, qa = a0 * a0 + a1 * a1;
            float sb2 = b0 + b1, qb2 = b0 * b0 + b1 * b1;
            #pragma unroll
            for (int off = 16; off; off >>= 1) {
                sa  += __shfl_xor_sync(0xffffffffu, sa,  off);
                qa  += __shfl_xor_sync(0xffffffffu, qa,  off);
                sb2 += __shfl_xor_sync(0xffffffffu, sb2, off);
                qb2 += __shfl_xor_sync(0xffffffffu, qb2, off);
            }
            float muA = sa * (1.0f / 64.0f);
            float rsA = rsqrtf(qa * (1.0f / 64.0f) - muA * muA + 1e-5f);
            float muB = sb2 * (1.0f / 64.0f);
            float rsB = rsqrtf(qb2 * (1.0f / 64.0f) - muB * muB + 1e-5f);
            float g0 = sm_g[lane], g1 = sm_g[lane + 32];
            float t0 = sm_bt[lane], t1 = sm_bt[lane + 32];
            stA(AHc, ALc, s0, lane,      (a0 - muA) * rsA * g0 + t0);
            stA(AHc, ALc, s0, lane + 32, (a1 - muA) * rsA * g1 + t1);
            stA(AHc, ALc, s1, lane,      (b0 - muB) * rsB * g0 + t0);
            stA(AHc, ALc, s1, lane + 32, (b1 - muB) * rsB * g1 + t1);
        }
        hbar(half);

        // ---- P3: QKV GEMM via mma.sync. warp wh -> n cols [wh*24, wh*24+24) ----
        {
            const int nb = wh * 24;
            float acc[4][3][4];
            #pragma unroll
            for (int mt = 0; mt < 4; mt++)
                #pragma unroll
                for (int nt = 0; nt < 3; nt++)
                    #pragma unroll
                    for (int i = 0; i < 4; i++) acc[mt][nt][i] = 0.f;
            const int arow = lane & 15, acb = (lane >> 4) * 8;
            const int brl = lane & 7,  bcb = ((lane >> 3) & 1) * 8;
            #pragma unroll
            for (int ks = 0; ks < 4; ks++) {
                u32 bh[3][2], bl[3][2];
                #pragma unroll
                for (int nt = 0; nt < 3; nt++) {
                    u32 off = SWZ((u32)((nb + nt * 8 + brl) * 128 + (ks * 16 + bcb) * 2));
                    ldsm2(bh[nt], BQH + off);
                    ldsm2(bl[nt], BQL + off);
                }
                #pragma unroll
                for (int mt = 0; mt < 4; mt++) {
                    u32 ah[4], al[4];
                    u32 off = SWZ((u32)((mt * 16 + arow) * 128 + (ks * 16 + acb) * 2));
                    ldsm4(ah, AHa + off);
                    ldsm4(al, ALa + off);
                    #pragma unroll
                    for (int nt = 0; nt < 3; nt++) {
                        mmabf(acc[mt][nt], ah, bh[nt]);
                        mmabf(acc[mt][nt], ah, bl[nt]);
                        mmabf(acc[mt][nt], al, bh[nt]);
                    }
                }
            }
            int gr = lane >> 2, gc = lane & 3;
            #pragma unroll
            for (int mt = 0; mt < 4; mt++)
                #pragma unroll
                for (int nt = 0; nt < 3; nt++) {
                    int j = nb + nt * 8 + 2 * gc;
                    float b0 = sm_qb[j], b1 = sm_qb[j + 1];
                    int s0 = mt * 16 + gr;
                    qU[s0 * 98 + (j >> 1)]       = pk2(acc[mt][nt][0] + b0, acc[mt][nt][1] + b1);
                    qU[(s0 + 8) * 98 + (j >> 1)] = pk2(acc[mt][nt][2] + b0, acc[mt][nt][3] + b1);
                }
        }
        hbar(half);

        // ---- P4: attention (scalar R8 mapping) -> ao as bf16 A tiles ----
        {
            const int h  = 2 * (wh & 3) + (lane >> 4);
            const int rb = (wh >> 2) * 2;
            const int sl = lane & 15;
            ull q[2][4];
            #pragma unroll
            for (int r = 0; r < 2; r++) {
                const ulonglong2* qp =
                    (const ulonglong2*)(qU + (sl + 16 * (rb + r)) * 98 + h * 4);
                ulonglong2 qa = qp[0], qb_ = qp[1];
                q[r][0] = qa.x; q[r][1] = qa.y; q[r][2] = qb_.x; q[r][3] = qb_.y;
            }
            ull acc[2][4];
            #pragma unroll
            for (int r = 0; r < 2; r++)
                #pragma unroll
                for (int d = 0; d < 4; d++) acc[r][d] = 0;
            float sums[2] = {0.f, 0.f};
            #pragma unroll 2
            for (int t = 0; t < 64; t += 2) {
                ull cb2[2];
                #pragma unroll
                for (int r = 0; r < 2; r++)
                    cb2[r] = *(const ull*)(sm_cb + (sl + 16 * (rb + r)) * 66 + t);
                #pragma unroll
                for (int u = 0; u < 2; u++) {
                    int tt = t + u;
                    const ulonglong2* kp = (const ulonglong2*)(qU + tt * 98 + 32 + h * 4);
                    ulonglong2 k0 = kp[0], k1 = kp[1];
                    const ulonglong2* vp = (const ulonglong2*)(qU + tt * 98 + 64 + h * 4);
                    ulonglong2 v0 = vp[0], v1 = vp[1];
                    #pragma unroll
                    for (int r = 0; r < 2; r++) {
                        ull d2 = mul2_(q[r][0], k0.x);
                        d2 = fma2_(q[r][1], k0.y, d2);
                        d2 = fma2_(q[r][2], k1.x, d2);
                        d2 = fma2_(q[r][3], k1.y, d2);
                        float dl, dh; up2(d2, dl, dh);
                        float cbl, cbh; up2(cb2[r], cbl, cbh);
                        float p = ex2_(fmaf(dl + dh, KSCALE, u ? cbh : cbl));
                        sums[r] += p;
                        ull pp = pk2(p, p);
                        acc[r][0] = fma2_(pp, v0.x, acc[r][0]);
                        acc[r][1] = fma2_(pp, v0.y, acc[r][1]);
                        acc[r][2] = fma2_(pp, v1.x, acc[r][2]);
                        acc[r][3] = fma2_(pp, v1.y, acc[r][3]);
                    }
                }
            }
            #pragma unroll
            for (int r = 0; r < 2; r++) {
                int row = sl + 16 * (rb + r);
                float inv = 1.0f / sums[r];
                ull iv = pk2(inv, inv);
                float p[8];
                up2(mul2_(acc[r][0], iv), p[0], p[1]);
                up2(mul2_(acc[r][1], iv), p[2], p[3]);
                up2(mul2_(acc[r][2], iv), p[4], p[5]);
                up2(mul2_(acc[r][3], iv), p[6], p[7]);
                u32 hw[4], lw[4];
                #pragma unroll
                for (int i = 0; i < 4; i++) {
                    hw[i] = bf2(p[2*i], p[2*i+1]);
                    lw[i] = bf2(p[2*i] - bflo(hw[i]), p[2*i+1] - bfhi(hw[i]));
                }
                u32 bo = SWZ((u32)(row * 128 + h * 16));
                *(uint4*)(AHc + bo) = make_uint4(hw[0], hw[1], hw[2], hw[3]);
                *(uint4*)(ALc + bo) = make_uint4(lw[0], lw[1], lw[2], lw[3]);
            }
        }
        hbar(half);

        // prefetch residual
        #pragma unroll
        for (int it = 0; it < 4; it++) {
            xreg[it] = xb4[tidh + 256 * it];
            preg[it] = pos4[tidh + 256 * it];
        }

        // ---- P5: out-proj via mma.sync. warp: mt = wh&3, nhalf = wh>>2 ----
        {
            const int mt = wh & 3, nh = wh >> 2;
            float acc[4][4];
            #pragma unroll
            for (int nt = 0; nt < 4; nt++)
                #pragma unroll
                for (int i = 0; i < 4; i++) acc[nt][i] = 0.f;
            const int arow = lane & 15, acb = (lane >> 4) * 8;
            const int brl = lane & 7,  bcb = ((lane >> 3) & 1) * 8;
            #pragma unroll
            for (int ks = 0; ks < 4; ks++) {
                u32 ah[4], al[4];
                u32 off = SWZ((u32)((mt * 16 + arow) * 128 + (ks * 16 + acb) * 2));
                ldsm4(ah, AHa + off);
                ldsm4(al, ALa + off);
                #pragma unroll
                for (int nt = 0; nt < 4; nt++) {
                    u32 bh[2], bl[2];
                    u32 boff = SWZ((u32)((nh * 32 + nt * 8 + brl) * 128 + (ks * 16 + bcb) * 2));
                    ldsm2(bh, BOH + boff);
                    ldsm2(bl, BOL + boff);
                    mmabf(acc[nt], ah, bh);
                    mmabf(acc[nt], ah, bl);
                    mmabf(acc[nt], al, bh);
                }
            }
            int gr = lane >> 2, gc = lane & 3;
            #pragma unroll
            for (int nt = 0; nt < 4; nt++) {
                int e0 = nh * 32 + nt * 8 + 2 * gc;
                int s0 = mt * 16 + gr;
                float ob0 = sm_ob[e0], ob1 = sm_ob[e0 + 1];
                yT[e0 * 65 + s0]           = acc[nt][0] + ob0;
                yT[(e0 + 1) * 65 + s0]     = acc[nt][1] + ob1;
                yT[e0 * 65 + s0 + 8]       = acc[nt][2] + ob0;
                yT[(e0 + 1) * 65 + s0 + 8] = acc[nt][3] + ob1;
            }
        }
        hbar(half);

        // ---- P6: residual + output ----
        float4* ob4 = (float4*)(gout + (size_t)b * 4096);
        #pragma unroll
        for (int it = 0; it < 4; it++) {
            int i4 = tidh + 256 * it;
            float4 xv = xreg[it], pv = preg[it];
            int e = i4 >> 4, s0 = (i4 & 15) * 4;
            const float* yp = yT + e * 65 + s0;
            float4 o;
            o.x = xv.x + pv.x + yp[0];
            o.y = xv.y + pv.y + yp[1];
            o.z = xv.z + pv.z + yp[2];
            o.w = xv.w + pv.w + yp[3];
            ob4[i4] = o;
        }
    }
}

extern "C" void kernel_launch(void* const* d_in, const int* in_sizes, int n_in,
                              void* d_out, int out_size)
{
    (void)in_sizes; (void)n_in; (void)out_size;
    cudaFuncSetAttribute(chess_attn_kernel,
                         cudaFuncAttributeMaxDynamicSharedMemorySize, SMEM_BYTES);
    hx_reset_counter<<<1, 1>>>();
    chess_attn_kernel<<<152, TPB, SMEM_BYTES>>>(
        (const float*)d_in[0], (const float*)d_in[1], (const float*)d_in[2],
        (const float*)d_in[3], (const float*)d_in[4], (const float*)d_in[5],
        (const float*)d_in[6], (const float*)d_in[7], (const float*)d_in[8],
        (float*)d_out);
}

// round 14
// speedup vs baseline: 2.3116x; 1.1742x over previous
#include <cuda_runtime.h>

// Round 14: full tensor-core pipeline. QKV + out-proj GEMMs via mma.sync
// (bf16 hi/lo 3-pass); attention QK^T and PV also on mma.sync using the
// C-frag == A/B-frag identities (warp w owns head w; Q/K never touch smem,
// V via warp-local transposed bf16 tile). Softmax fused (exp2, no max).

#define TPB 512
#define NBATCH 4096
typedef unsigned long long ull;
typedef unsigned int u32;

__device__ int g_next_batch;
__global__ void hx_reset_counter() { g_next_batch = 0; }

__device__ __forceinline__ ull pk2(float x, float y) {
    ull r; asm("mov.b64 %0,{%1,%2};" : "=l"(r) : "f"(x), "f"(y)); return r;
}
__device__ __forceinline__ void up2(ull p, float& x, float& y) {
    asm("mov.b64 {%0,%1},%2;" : "=f"(x), "=f"(y) : "l"(p));
}
__device__ __forceinline__ float ex2_(float x) {
    float r; asm("ex2.approx.f32 %0,%1;" : "=f"(r) : "f"(x)); return r;
}
__device__ __forceinline__ void hbar(int half) {
    asm volatile("bar.sync %0, 256;" :: "r"(1 + half) : "memory");
}
__device__ __forceinline__ u32 s2u(const void* p) {
    u32 a; asm("{ .reg .u64 t; cvta.to.shared.u64 t, %1; cvt.u32.u64 %0, t; }"
               : "=r"(a) : "l"(p));
    return a;
}
__device__ __forceinline__ u32 bf2(float lo, float hi) {
    u32 r; asm("cvt.rn.bf16x2.f32 %0, %1, %2;" : "=r"(r) : "f"(hi), "f"(lo)); return r;
}
__device__ __forceinline__ float bflo(u32 p) { return __uint_as_float(p << 16); }
__device__ __forceinline__ float bfhi(u32 p) { return __uint_as_float(p & 0xFFFF0000u); }
__device__ __forceinline__ void ldsm4(u32* r, u32 a) {
    asm volatile("ldmatrix.sync.aligned.m8n8.x4.shared.b16 {%0,%1,%2,%3}, [%4];"
        : "=r"(r[0]), "=r"(r[1]), "=r"(r[2]), "=r"(r[3]) : "r"(a));
}
__device__ __forceinline__ void ldsm2(u32* r, u32 a) {
    asm volatile("ldmatrix.sync.aligned.m8n8.x2.shared.b16 {%0,%1}, [%2];"
        : "=r"(r[0]), "=r"(r[1]) : "r"(a));
}
__device__ __forceinline__ void mmabf(float* c, const u32* a, const u32* b) {
    asm volatile("mma.sync.aligned.m16n8k16.row.col.f32.bf16.bf16.f32 "
        "{%0,%1,%2,%3},{%4,%5,%6,%7},{%8,%9},{%0,%1,%2,%3};"
        : "+f"(c[0]), "+f"(c[1]), "+f"(c[2]), "+f"(c[3])
        : "r"(a[0]), "r"(a[1]), "r"(a[2]), "r"(a[3]), "r"(b[0]), "r"(b[1]));
}
__device__ __forceinline__ void mmab8(float* c, const u32* a, u32 b) {
    asm volatile("mma.sync.aligned.m16n8k8.row.col.f32.bf16.bf16.f32 "
        "{%0,%1,%2,%3},{%4,%5},{%6},{%0,%1,%2,%3};"
        : "+f"(c[0]), "+f"(c[1]), "+f"(c[2]), "+f"(c[3])
        : "r"(a[0]), "r"(a[1]), "r"(b));
}
__device__ __forceinline__ void sts16(u32 a, unsigned short v) {
    asm volatile("st.shared.u16 [%0], %1;" :: "r"(a), "h"(v));
}

#define LOG2E  1.4426950408889634f
#define KSCALE (0.35355339059327373f * 1.4426950408889634f)
#define SWZ(b) ((b) ^ (((b) >> 3) & 0x70))

// smem offsets (floats)
#define OFF_BQH 0        // 6144  qkv_w hi  [192][64] bf16 SW128
#define OFF_BQL 6144
#define OFF_BOH 12288    // 2048  out_w hi  [64][64]
#define OFF_BOL 14336
#define OFF_AH0 16384    // 2048/tile: LN-out (then ao) bf16 per half
#define OFF_AL0 18432
#define OFF_AH1 20480
#define OFF_AL1 22528
#define OFF_Q0  24576    // per half: VT_H[0,2048) VT_L[2048,4096) xst/yT[4096,8256)
#define OFF_Q1  37120
#define OFF_CB  49664    // 4224  chess bias * log2e, stride 66
#define OFF_QB  53888    // 192
#define OFF_OB  54080    // 64
#define OFF_G   54144    // 64
#define OFF_BT  54208    // 64
#define OFF_BB  54272    // 8
#define SMEM_FLOATS 54280
#define SMEM_BYTES  (SMEM_FLOATS * 4)

__device__ __forceinline__ void stA(char* AH, char* AL, int row, int e, float v) {
    u32 hp = bf2(v, 0.f);
    u32 lp = bf2(v - bflo(hp), 0.f);
    u32 b = SWZ((u32)(row * 128 + e * 2));
    *(unsigned short*)(AH + b) = (unsigned short)hp;
    *(unsigned short*)(AL + b) = (unsigned short)lp;
}

extern "C" __global__ void __launch_bounds__(TPB)
chess_attn_kernel(const float* __restrict__ gx,
                  const float* __restrict__ gpos,
                  const float* __restrict__ ggamma,
                  const float* __restrict__ gbeta,
                  const float* __restrict__ gqkvw,
                  const float* __restrict__ gqkvb,
                  const float* __restrict__ goutw,
                  const float* __restrict__ goutb,
                  const float* __restrict__ gcb,
                  float* __restrict__ gout)
{
    extern __shared__ float sm[];
    float* sm_cb = sm + OFF_CB;
    float* sm_qb = sm + OFF_QB;
    float* sm_ob = sm + OFF_OB;
    float* sm_g  = sm + OFF_G;
    float* sm_bt = sm + OFF_BT;
    int*   sm_bb = (int*)(sm + OFF_BB);

    const int tid  = threadIdx.x;
    const int lane = tid & 31;
    const int warp = tid >> 5;
    const int half = warp >> 3;
    const int tidh = tid & 255;
    const int wh   = warp & 7;
    const int gr   = lane >> 2, gc = lane & 3;
    const u32 sb   = s2u(sm);

    const int regoff = half ? OFF_Q1 : OFF_Q0;
    float* xst = sm + regoff + 4096;           // [e][s] stride 65
    float* yT  = xst;                          // [e][s] stride 65 (reuse)
    char*  AHc = (char*)(sm + (half ? OFF_AH1 : OFF_AH0));
    char*  ALc = (char*)(sm + (half ? OFF_AL1 : OFF_AL0));
    const u32 AHa  = sb + (half ? OFF_AH1 : OFF_AH0) * 4;
    const u32 ALa  = sb + (half ? OFF_AL1 : OFF_AL0) * 4;
    const u32 BQH  = sb + OFF_BQH * 4, BQL = sb + OFF_BQL * 4;
    const u32 BOH  = sb + OFF_BOH * 4, BOL = sb + OFF_BOL * 4;
    const u32 VTHa = sb + regoff * 4;
    const u32 VTLa = VTHa + 8192;
    ull* qbU = (ull*)sm_qb;

    // stage weights as bf16 hi/lo SW128 tiles
    char* BQHc = (char*)(sm + OFF_BQH);
    char* BQLc = (char*)(sm + OFF_BQL);
    char* BOHc = (char*)(sm + OFF_BOH);
    char* BOLc = (char*)(sm + OFF_BOL);
    for (int i = tid; i < 192 * 64; i += TPB) {
        int j = i >> 6, e = i & 63;
        float v = gqkvw[i];
        u32 hp = bf2(v, 0.f), lp = bf2(v - bflo(hp), 0.f);
        u32 b = SWZ((u32)(j * 128 + e * 2));
        *(unsigned short*)(BQHc + b) = (unsigned short)hp;
        *(unsigned short*)(BQLc + b) = (unsigned short)lp;
    }
    for (int i = tid; i < 64 * 64; i += TPB) {
        int e = i >> 6, t = i & 63;
        float v = goutw[i];
        u32 hp = bf2(v, 0.f), lp = bf2(v - bflo(hp), 0.f);
        u32 b = SWZ((u32)(e * 128 + t * 2));
        *(unsigned short*)(BOHc + b) = (unsigned short)hp;
        *(unsigned short*)(BOLc + b) = (unsigned short)lp;
    }
    for (int i = tid; i < 64 * 64; i += TPB) {
        int s = i >> 6, t = i & 63;
        sm_cb[s * 66 + t] = gcb[i] * LOG2E;
    }
    if (tid < 192) sm_qb[tid] = gqkvb[tid];
    if (tid < 64) { sm_ob[tid] = goutb[tid]; sm_g[tid] = ggamma[tid]; sm_bt[tid] = gbeta[tid]; }
    __syncthreads();

    const float4* pos4 = (const float4*)gpos;

    while (true) {
        hbar(half);
        if (tidh == 0) sm_bb[half] = atomicAdd(&g_next_batch, 1);
        hbar(half);
        int b = sm_bb[half];
        if (b >= NBATCH) break;
        const float4* xb4 = (const float4*)(gx + (size_t)b * 4096);

        // ---- P1: x + pos -> xst [e][s] ----
        float4 xreg[4], preg[4];
        #pragma unroll
        for (int it = 0; it < 4; it++) {
            int i4 = tidh + 256 * it;
            float4 xv = xb4[i4], pv = pos4[i4];
            int e = i4 >> 4, s0 = (i4 & 15) * 4;
            float* p = xst + e * 65 + s0;
            p[0] = xv.x + pv.x; p[1] = xv.y + pv.y;
            p[2] = xv.z + pv.z; p[3] = xv.w + pv.w;
        }
        hbar(half);

        // ---- P2: LayerNorm -> A tiles (bf16 hi/lo) ----
        #pragma unroll
        for (int k = 0; k < 4; k++) {
            int s0 = wh * 8 + 2 * k, s1 = s0 + 1;
            float a0 = xst[lane * 65 + s0];
            float a1 = xst[(lane + 32) * 65 + s0];
            float b0 = xst[lane * 65 + s1];
            float b1 = xst[(lane + 32) * 65 + s1];
            float sa = a0 + a1, qa = a0 * a0 + a1 * a1;
            float sb2 = b0 + b1, qb2 = b0 * b0 + b1 * b1;
            #pragma unroll
            for (int off = 16; off; off >>= 1) {
                sa  += __shfl_xor_sync(0xffffffffu, sa,  off);
                qa  += __shfl_xor_sync(0xffffffffu, qa,  off);
                sb2 += __shfl_xor_sync(0xffffffffu, sb2, off);
                qb2 += __shfl_xor_sync(0xffffffffu, qb2, off);
            }
            float muA = sa * (1.0f / 64.0f);
            float rsA = rsqrtf(qa * (1.0f / 64.0f) - muA * muA + 1e-5f);
            float muB = sb2 * (1.0f / 64.0f);
            float rsB = rsqrtf(qb2 * (1.0f / 64.0f) - muB * muB + 1e-5f);
            float g0 = sm_g[lane], g1 = sm_g[lane + 32];
            float t0 = sm_bt[lane], t1 = sm_bt[lane + 32];
            stA(AHc, ALc, s0, lane,      (a0 - muA) * rsA * g0 + t0);
            stA(AHc, ALc, s0, lane + 32, (a1 - muA) * rsA * g1 + t1);
            stA(AHc, ALc, s1, lane,      (b0 - muB) * rsB * g0 + t0);
            stA(AHc, ALc, s1, lane + 32, (b1 - muB) * rsB * g1 + t1);
        }
        hbar(half);

        // ---- P3: QKV mma. warp wh owns head wh: n-tiles {8wh, 64+8wh, 128+8wh} ----
        float acc[4][3][4];
        #pragma unroll
        for (int mt = 0; mt < 4; mt++)
            #pragma unroll
            for (int g = 0; g < 3; g++)
                #pragma unroll
                for (int i = 0; i < 4; i++) acc[mt][g][i] = 0.f;
        {
            const int arow = lane & 15, acb = (lane >> 4) * 8;
            const int brl = lane & 7, bcb = ((lane >> 3) & 1) * 8;
            const int nbs0 = 8 * wh, nbs1 = 64 + 8 * wh, nbs2 = 128 + 8 * wh;
            #pragma unroll
            for (int ks = 0; ks < 4; ks++) {
                u32 bh[3][2], bl[3][2];
                u32 o0 = SWZ((u32)((nbs0 + brl) * 128 + (ks * 16 + bcb) * 2));
                u32 o1 = SWZ((u32)((nbs1 + brl) * 128 + (ks * 16 + bcb) * 2));
                u32 o2 = SWZ((u32)((nbs2 + brl) * 128 + (ks * 16 + bcb) * 2));
                ldsm2(bh[0], BQH + o0); ldsm2(bl[0], BQL + o0);
                ldsm2(bh[1], BQH + o1); ldsm2(bl[1], BQL + o1);
                ldsm2(bh[2], BQH + o2); ldsm2(bl[2], BQL + o2);
                #pragma unroll
                for (int mt = 0; mt < 4; mt++) {
                    u32 ah[4], al[4];
                    u32 off = SWZ((u32)((mt * 16 + arow) * 128 + (ks * 16 + acb) * 2));
                    ldsm4(ah, AHa + off);
                    ldsm4(al, ALa + off);
                    #pragma unroll
                    for (int g = 0; g < 3; g++) {
                        mmabf(acc[mt][g], ah, bh[g]);
                        mmabf(acc[mt][g], ah, bl[g]);
                        mmabf(acc[mt][g], al, bh[g]);
                    }
                }
            }
            // biases (col-pair for this warp's head)
            float bq0, bq1, bk0, bk1, bv0, bv1;
            up2(qbU[4 * wh + gc], bq0, bq1);
            up2(qbU[32 + 4 * wh + gc], bk0, bk1);
            up2(qbU[64 + 4 * wh + gc], bv0, bv1);
            #pragma unroll
            for (int mt = 0; mt < 4; mt++) {
                acc[mt][0][0] += bq0; acc[mt][0][1] += bq1;
                acc[mt][0][2] += bq0; acc[mt][0][3] += bq1;
                acc[mt][1][0] += bk0; acc[mt][1][1] += bk1;
                acc[mt][1][2] += bk0; acc[mt][1][3] += bk1;
                acc[mt][2][0] += bv0; acc[mt][2][1] += bv1;
                acc[mt][2][2] += bv0; acc[mt][2][3] += bv1;
            }
        }

        // V -> warp-local transposed bf16 hi/lo tile VT[8wh+d][t]
        #pragma unroll
        for (int mt = 0; mt < 4; mt++)
            #pragma unroll
            for (int i = 0; i < 4; i++) {
                float v = acc[mt][2][i];
                int d = 2 * gc + (i & 1);
                int t = 16 * mt + gr + ((i & 2) ? 8 : 0);
                u32 hp = bf2(v, 0.f);
                u32 lp = bf2(v - bflo(hp), 0.f);
                u32 off = SWZ((u32)((8 * wh + d) * 128 + t * 2));
                sts16(VTHa + off, (unsigned short)hp);
                sts16(VTLa + off, (unsigned short)lp);
            }

        // Q A-frags + K B-frags (hi/lo) in registers
        u32 qh[4][2], ql[4][2], kbh[8], kbl[8];
        #pragma unroll
        for (int mt = 0; mt < 4; mt++) {
            float q0 = acc[mt][0][0], q1 = acc[mt][0][1];
            float q2 = acc[mt][0][2], q3 = acc[mt][0][3];
            qh[mt][0] = bf2(q0, q1);
            ql[mt][0] = bf2(q0 - bflo(qh[mt][0]), q1 - bfhi(qh[mt][0]));
            qh[mt][1] = bf2(q2, q3);
            ql[mt][1] = bf2(q2 - bflo(qh[mt][1]), q3 - bfhi(qh[mt][1]));
            float k0 = acc[mt][1][0], k1 = acc[mt][1][1];
            float k2 = acc[mt][1][2], k3 = acc[mt][1][3];
            kbh[2 * mt]     = bf2(k0, k1);
            kbl[2 * mt]     = bf2(k0 - bflo(kbh[2 * mt]), k1 - bfhi(kbh[2 * mt]));
            kbh[2 * mt + 1] = bf2(k2, k3);
            kbl[2 * mt + 1] = bf2(k2 - bflo(kbh[2 * mt + 1]), k3 - bfhi(kbh[2 * mt + 1]));
        }
        hbar(half);        // P3 A-tile reads complete before ao overwrites AH/AL

        // ---- P4: attention on tensor cores, streaming over t ----
        #pragma unroll
        for (int mh = 0; mh < 2; mh++) {
            float oacc[2][4];
            float rs[2][2];
            #pragma unroll
            for (int mi = 0; mi < 2; mi++) {
                oacc[mi][0] = oacc[mi][1] = oacc[mi][2] = oacc[mi][3] = 0.f;
                rs[mi][0] = rs[mi][1] = 0.f;
            }
            #pragma unroll
            for (int ntp = 0; ntp < 4; ntp++) {
                u32 vbh[2], vbl[2];
                {
                    int l = lane & 15;
                    u32 vo = SWZ((u32)((8 * wh + (l & 7)) * 128
                                       + (16 * ntp + ((l >> 3) << 3)) * 2));
                    ldsm2(vbh, VTHa + vo);
                    ldsm2(vbl, VTLa + vo);
                }
                #pragma unroll
                for (int mi = 0; mi < 2; mi++) {
                    int mt = 2 * mh + mi;
                    float s0[4] = {0.f, 0.f, 0.f, 0.f};
                    float s1[4] = {0.f, 0.f, 0.f, 0.f};
                    mmab8(s0, qh[mt], kbh[2 * ntp]);
                    mmab8(s0, ql[mt], kbh[2 * ntp]);
                    mmab8(s0, qh[mt], kbl[2 * ntp]);
                    mmab8(s1, qh[mt], kbh[2 * ntp + 1]);
                    mmab8(s1, ql[mt], kbh[2 * ntp + 1]);
                    mmab8(s1, qh[mt], kbl[2 * ntp + 1]);
                    int r0 = 16 * mt + gr;
                    const float* c0p = sm_cb + r0 * 66 + 16 * ntp + 2 * gc;
                    const float* c1p = sm_cb + (r0 + 8) * 66 + 16 * ntp + 2 * gc;
                    float c00, c01, c10, c11, c20, c21, c30, c31;
                    up2(*(const ull*)c0p, c00, c01);
                    up2(*(const ull*)c1p, c10, c11);
                    up2(*(const ull*)(c0p + 8), c20, c21);
                    up2(*(const ull*)(c1p + 8), c30, c31);
                    float p00 = ex2_(fmaf(s0[0], KSCALE, c00));
                    float p01 = ex2_(fmaf(s0[1], KSCALE, c01));
                    float p02 = ex2_(fmaf(s0[2], KSCALE, c10));
                    float p03 = ex2_(fmaf(s0[3], KSCALE, c11));
                    float p10 = ex2_(fmaf(s1[0], KSCALE, c20));
                    float p11 = ex2_(fmaf(s1[1], KSCALE, c21));
                    float p12 = ex2_(fmaf(s1[2], KSCALE, c30));
                    float p13 = ex2_(fmaf(s1[3], KSCALE, c31));
                    rs[mi][0] += (p00 + p01) + (p10 + p11);
                    rs[mi][1] += (p02 + p03) + (p12 + p13);
                    u32 pa[4], pl_[4];
                    pa[0] = bf2(p00, p01);
                    pa[1] = bf2(p02, p03);
                    pa[2] = bf2(p10, p11);
                    pa[3] = bf2(p12, p13);
                    pl_[0] = bf2(p00 - bflo(pa[0]), p01 - bfhi(pa[0]));
                    pl_[1] = bf2(p02 - bflo(pa[1]), p03 - bfhi(pa[1]));
                    pl_[2] = bf2(p10 - bflo(pa[2]), p11 - bfhi(pa[2]));
                    pl_[3] = bf2(p12 - bflo(pa[3]), p13 - bfhi(pa[3]));
                    mmabf(oacc[mi], pa, vbh);
                    mmabf(oacc[mi], pl_, vbh);
                    mmabf(oacc[mi], pa, vbl);
                }
            }
            // rowsum reduce (quad), scale, write ao -> AH/AL
            #pragma unroll
            for (int mi = 0; mi < 2; mi++) {
                int r0 = 16 * (2 * mh + mi) + gr;
                float ra = rs[mi][0], rb2 = rs[mi][1];
                ra  += __shfl_xor_sync(0xffffffffu, ra, 1);
                ra  += __shfl_xor_sync(0xffffffffu, ra, 2);
                rb2 += __shfl_xor_sync(0xffffffffu, rb2, 1);
                rb2 += __shfl_xor_sync(0xffffffffu, rb2, 2);
                float i0 = 1.0f / ra, i1 = 1.0f / rb2;
                float o0 = oacc[mi][0] * i0, o1 = oacc[mi][1] * i0;
                float o2 = oacc[mi][2] * i1, o3 = oacc[mi][3] * i1;
                u32 h0 = bf2(o0, o1);
                u32 l0 = bf2(o0 - bflo(h0), o1 - bfhi(h0));
                u32 h1 = bf2(o2, o3);
                u32 l1 = bf2(o2 - bflo(h1), o3 - bfhi(h1));
                u32 co = (u32)((8 * wh + 2 * gc) * 2);
                *(u32*)(AHc + SWZ((u32)(r0 * 128) + co)) = h0;
                *(u32*)(ALc + SWZ((u32)(r0 * 128) + co)) = l0;
                *(u32*)(AHc + SWZ((u32)((r0 + 8) * 128) + co)) = h1;
                *(u32*)(ALc + SWZ((u32)((r0 + 8) * 128) + co)) = l1;
            }
        }
        hbar(half);

        // prefetch residual
        #pragma unroll
        for (int it = 0; it < 4; it++) {
            xreg[it] = xb4[tidh + 256 * it];
            preg[it] = pos4[tidh + 256 * it];
        }

        // ---- P5: out-proj via mma.sync (warp: mt = wh&3, nh = wh>>2) ----
        {
            const int mt = wh & 3, nh = wh >> 2;
            float oa[4][4];
            #pragma unroll
            for (int nt = 0; nt < 4; nt++)
                #pragma unroll
                for (int i = 0; i < 4; i++) oa[nt][i] = 0.f;
            const int arow = lane & 15, acb = (lane >> 4) * 8;
            const int brl = lane & 7, bcb = ((lane >> 3) & 1) * 8;
            #pragma unroll
            for (int ks = 0; ks < 4; ks++) {
                u32 ah[4], al[4];
                u32 off = SWZ((u32)((mt * 16 + arow) * 128 + (ks * 16 + acb) * 2));
                ldsm4(ah, AHa + off);
                ldsm4(al, ALa + off);
                #pragma unroll
                for (int nt = 0; nt < 4; nt++) {
                    u32 bh[2], bl[2];
                    u32 boff = SWZ((u32)((nh * 32 + nt * 8 + brl) * 128 + (ks * 16 + bcb) * 2));
                    ldsm2(bh, BOH + boff);
                    ldsm2(bl, BOL + boff);
                    mmabf(oa[nt], ah, bh);
                    mmabf(oa[nt], ah, bl);
                    mmabf(oa[nt], al, bh);
                }
            }
            #pragma unroll
            for (int nt = 0; nt < 4; nt++) {
                int e0 = nh * 32 + nt * 8 + 2 * gc;
                int s0 = mt * 16 + gr;
                float ob0 = sm_ob[e0], ob1 = sm_ob[e0 + 1];
                yT[e0 * 65 + s0]           = oa[nt][0] + ob0;
                yT[(e0 + 1) * 65 + s0]     = oa[nt][1] + ob1;
                yT[e0 * 65 + s0 + 8]       = oa[nt][2] + ob0;
                yT[(e0 + 1) * 65 + s0 + 8] = oa[nt][3] + ob1;
            }
        }
        hbar(half);

        // ---- P6: residual + output ----
        float4* ob4 = (float4*)(gout + (size_t)b * 4096);
        #pragma unroll
        for (int it = 0; it < 4; it++) {
            int i4 = tidh + 256 * it;
            float4 xv = xreg[it], pv = preg[it];
            int e = i4 >> 4, s0 = (i4 & 15) * 4;
            const float* yp = yT + e * 65 + s0;
            float4 o;
            o.x = xv.x + pv.x + yp[0];
            o.y = xv.y + pv.y + yp[1];
            o.z = xv.z + pv.z + yp[2];
            o.w = xv.w + pv.w + yp[3];
            ob4[i4] = o;
        }
    }
}

extern "C" void kernel_launch(void* const* d_in, const int* in_sizes, int n_in,
                              void* d_out, int out_size)
{
    (void)in_sizes; (void)n_in; (void)out_size;
    cudaFuncSetAttribute(chess_attn_kernel,
                         cudaFuncAttributeMaxDynamicSharedMemorySize, SMEM_BYTES);
    hx_reset_counter<<<1, 1>>>();
    chess_attn_kernel<<<152, TPB, SMEM_BYTES>>>(
        (const float*)d_in[0], (const float*)d_in[1], (const float*)d_in[2],
        (const float*)d_in[3], (const float*)d_in[4], (const float*)d_in[5],
        (const float*)d_in[6], (const float*)d_in[7], (const float*)d_in[8],
        (float*)d_out);
}

// round 16
// speedup vs baseline: 2.6439x; 1.1438x over previous
#include <cuda_runtime.h>

// Round 15: R14 tensor pipeline + smem-instruction diet.
// - yT de-aliased from xst -> residual comes from xst, x loaded ONCE
// - pos in smem; chess bias in fragment-major layout (LDS.128)
// - V tile t-major u32 pairs + ldmatrix.trans; V frags hoisted
// - k-paired B ldsm in both GEMMs; counter atomic hidden before P5

#define TPB 512
#define NBATCH 4096
typedef unsigned long long ull;
typedef unsigned int u32;

__device__ int g_next_batch;
__global__ void hx_reset_counter() { g_next_batch = 0; }

__device__ __forceinline__ float ex2_(float x) {
    float r; asm("ex2.approx.f32 %0,%1;" : "=f"(r) : "f"(x)); return r;
}
__device__ __forceinline__ void hbar(int half) {
    asm volatile("bar.sync %0, 256;" :: "r"(1 + half) : "memory");
}
__device__ __forceinline__ u32 s2u(const void* p) {
    u32 a; asm("{ .reg .u64 t; cvta.to.shared.u64 t, %1; cvt.u32.u64 %0, t; }"
               : "=r"(a) : "l"(p));
    return a;
}
__device__ __forceinline__ u32 bf2(float lo, float hi) {
    u32 r; asm("cvt.rn.bf16x2.f32 %0, %1, %2;" : "=r"(r) : "f"(hi), "f"(lo)); return r;
}
__device__ __forceinline__ float bflo(u32 p) { return __uint_as_float(p << 16); }
__device__ __forceinline__ float bfhi(u32 p) { return __uint_as_float(p & 0xFFFF0000u); }
__device__ __forceinline__ void up2(ull p, float& x, float& y) {
    asm("mov.b64 {%0,%1},%2;" : "=f"(x), "=f"(y) : "l"(p));
}
__device__ __forceinline__ void ldsm4(u32* r, u32 a) {
    asm volatile("ldmatrix.sync.aligned.m8n8.x4.shared.b16 {%0,%1,%2,%3}, [%4];"
        : "=r"(r[0]), "=r"(r[1]), "=r"(r[2]), "=r"(r[3]) : "r"(a));
}
__device__ __forceinline__ void ldsm2t(u32* r, u32 a) {
    asm volatile("ldmatrix.sync.aligned.m8n8.x2.trans.shared.b16 {%0,%1}, [%2];"
        : "=r"(r[0]), "=r"(r[1]) : "r"(a));
}
__device__ __forceinline__ void mmabf(float* c, const u32* a, const u32* b) {
    asm volatile("mma.sync.aligned.m16n8k16.row.col.f32.bf16.bf16.f32 "
        "{%0,%1,%2,%3},{%4,%5,%6,%7},{%8,%9},{%0,%1,%2,%3};"
        : "+f"(c[0]), "+f"(c[1]), "+f"(c[2]), "+f"(c[3])
        : "r"(a[0]), "r"(a[1]), "r"(a[2]), "r"(a[3]), "r"(b[0]), "r"(b[1]));
}
__device__ __forceinline__ void mmab8(float* c, const u32* a, u32 b) {
    asm volatile("mma.sync.aligned.m16n8k8.row.col.f32.bf16.bf16.f32 "
        "{%0,%1,%2,%3},{%4,%5},{%6},{%0,%1,%2,%3};"
        : "+f"(c[0]), "+f"(c[1]), "+f"(c[2]), "+f"(c[3])
        : "r"(a[0]), "r"(a[1]), "r"(b));
}

#define LOG2E  1.4426950408889634f
#define KSCALE (0.35355339059327373f * 1.4426950408889634f)
#define SWZ(b) ((b) ^ (((b) >> 3) & 0x70))

// smem offsets (floats); total 57992 fl = 231,968 B < 232,448 cap
#define OFF_BQH 0        // 6144  qkv_w hi [192][64] bf16 SW128
#define OFF_BQL 6144
#define OFF_BOH 12288    // 2048  out_w hi [64][64]
#define OFF_BOL 14336
#define OFF_AH0 16384    // 2048/tile: LN-out/ao bf16 per half
#define OFF_AL0 18432
#define OFF_AH1 20480
#define OFF_AL1 22528
#define OFF_R0  24576    // 12416/half: VTH[0,8192)B VTL[8192,16384)B xst@+4096f yT@+8256f
#define OFF_R1  36992
#define OFF_CBF 49408    // 4096  chess bias, fragment-major, *LOG2E
#define OFF_POS 53504    // 4096
#define OFF_QB  57600    // 192
#define OFF_OB  57792    // 64
#define OFF_G   57856    // 64
#define OFF_BT  57920    // 64
#define OFF_BB  57984    // 8
#define SMEM_FLOATS 57992
#define SMEM_BYTES  (SMEM_FLOATS * 4)

__device__ __forceinline__ void stA(char* AH, char* AL, int row, int e, float v) {
    u32 hp = bf2(v, 0.f);
    u32 lp = bf2(v - bflo(hp), 0.f);
    u32 b = SWZ((u32)(row * 128 + e * 2));
    *(unsigned short*)(AH + b) = (unsigned short)hp;
    *(unsigned short*)(AL + b) = (unsigned short)lp;
}

extern "C" __global__ void __launch_bounds__(TPB)
chess_attn_kernel(const float* __restrict__ gx,
                  const float* __restrict__ gpos,
                  const float* __restrict__ ggamma,
                  const float* __restrict__ gbeta,
                  const float* __restrict__ gqkvw,
                  const float* __restrict__ gqkvb,
                  const float* __restrict__ goutw,
                  const float* __restrict__ goutb,
                  const float* __restrict__ gcb,
                  float* __restrict__ gout)
{
    extern __shared__ float sm[];
    float* sm_qb = sm + OFF_QB;
    float* sm_ob = sm + OFF_OB;
    float* sm_g  = sm + OFF_G;
    float* sm_bt = sm + OFF_BT;
    int*   sm_bb = (int*)(sm + OFF_BB);

    const int tid  = threadIdx.x;
    const int lane = tid & 31;
    const int warp = tid >> 5;
    const int half = warp >> 3;
    const int tidh = tid & 255;
    const int wh   = warp & 7;
    const int gr   = lane >> 2, gc = lane & 3;
    const u32 sb   = s2u(sm);

    const int regbase = half ? OFF_R1 : OFF_R0;
    float* xst = sm + regbase + 4096;          // [e][s] stride 65 (x+pos, residual)
    float* yT  = sm + regbase + 8256;          // [e][s] stride 65
    char*  AHc = (char*)(sm + (half ? OFF_AH1 : OFF_AH0));
    char*  ALc = (char*)(sm + (half ? OFF_AL1 : OFF_AL0));
    char*  VTHc = (char*)(sm + regbase);
    char*  VTLc = VTHc + 8192;
    const u32 AHa  = sb + (half ? OFF_AH1 : OFF_AH0) * 4;
    const u32 ALa  = sb + (half ? OFF_AL1 : OFF_AL0) * 4;
    const u32 BQH  = sb + OFF_BQH * 4, BQL = sb + OFF_BQL * 4;
    const u32 BOH  = sb + OFF_BOH * 4, BOL = sb + OFF_BOL * 4;
    const u32 VTHa = sb + regbase * 4;
    const u32 VTLa = VTHa + 8192;
    ull* qbU = (ull*)sm_qb;

    // ---- stage constants ----
    char* BQHc = (char*)(sm + OFF_BQH);
    char* BQLc = (char*)(sm + OFF_BQL);
    char* BOHc = (char*)(sm + OFF_BOH);
    char* BOLc = (char*)(sm + OFF_BOL);
    for (int i = tid; i < 192 * 64; i += TPB) {
        int j = i >> 6, e = i & 63;
        float v = gqkvw[i];
        u32 hp = bf2(v, 0.f), lp = bf2(v - bflo(hp), 0.f);
        u32 b = SWZ((u32)(j * 128 + e * 2));
        *(unsigned short*)(BQHc + b) = (unsigned short)hp;
        *(unsigned short*)(BQLc + b) = (unsigned short)lp;
    }
    for (int i = tid; i < 64 * 64; i += TPB) {
        int e = i >> 6, t = i & 63;
        float v = goutw[i];
        u32 hp = bf2(v, 0.f), lp = bf2(v - bflo(hp), 0.f);
        u32 b = SWZ((u32)(e * 128 + t * 2));
        *(unsigned short*)(BOHc + b) = (unsigned short)hp;
        *(unsigned short*)(BOLc + b) = (unsigned short)lp;
    }
    // chess bias: fragment-major cbF[((mt*4+ntp)*32+lane)*8 + j]
    for (int i = tid; i < 4096; i += TPB) {
        int j = i & 7, ln = (i >> 3) & 31, pr = i >> 8;
        int mt = pr >> 2, ntp = pr & 3;
        int grr = ln >> 2, gcc = ln & 3;
        int row = 16 * mt + grr + ((j >> 1) & 1) * 8;
        int col = 16 * ntp + 2 * gcc + (j & 1) + ((j >> 2) & 1) * 8;
        sm[OFF_CBF + i] = gcb[row * 64 + col] * LOG2E;
    }
    for (int i = tid; i < 4096; i += TPB) sm[OFF_POS + i] = gpos[i];
    if (tid < 192) sm_qb[tid] = gqkvb[tid];
    if (tid < 64) { sm_ob[tid] = goutb[tid]; sm_g[tid] = ggamma[tid]; sm_bt[tid] = gbeta[tid]; }
    __syncthreads();

    const float4* posS4 = (const float4*)(sm + OFF_POS);
    const float4* cbF4  = (const float4*)(sm + OFF_CBF);

    // initial batch fetch
    hbar(half);
    if (tidh == 0) sm_bb[half] = atomicAdd(&g_next_batch, 1);
    hbar(half);
    int b = sm_bb[half];

    while (b < NBATCH) {
        const float4* xb4 = (const float4*)(gx + (size_t)b * 4096);

        // ---- P1: x (LDG) + pos (smem) -> xst [e][s] stride 65 ----
        #pragma unroll
        for (int it = 0; it < 4; it++) {
            int i4 = tidh + 256 * it;
            float4 xv = xb4[i4], pv = posS4[i4];
            int e = i4 >> 4, s0 = (i4 & 15) * 4;
            float* p = xst + e * 65 + s0;
            p[0] = xv.x + pv.x; p[1] = xv.y + pv.y;
            p[2] = xv.z + pv.z; p[3] = xv.w + pv.w;
        }
        hbar(half);

        // ---- P2: LayerNorm -> A tiles (bf16 hi/lo); xst preserved ----
        #pragma unroll
        for (int k = 0; k < 4; k++) {
            int s0 = wh * 8 + 2 * k, s1 = s0 + 1;
            float a0 = xst[lane * 65 + s0];
            float a1 = xst[(lane + 32) * 65 + s0];
            float b0 = xst[lane * 65 + s1];
            float b1 = xst[(lane + 32) * 65 + s1];
            float sa = a0 + a1, qa = a0 * a0 + a1 * a1;
            float sb2 = b0 + b1, qb2 = b0 * b0 + b1 * b1;
            #pragma unroll
            for (int off = 16; off; off >>= 1) {
                sa  += __shfl_xor_sync(0xffffffffu, sa,  off);
                qa  += __shfl_xor_sync(0xffffffffu, qa,  off);
                sb2 += __shfl_xor_sync(0xffffffffu, sb2, off);
                qb2 += __shfl_xor_sync(0xffffffffu, qb2, off);
            }
            float muA = sa * (1.0f / 64.0f);
            float rsA = rsqrtf(qa * (1.0f / 64.0f) - muA * muA + 1e-5f);
            float muB = sb2 * (1.0f / 64.0f);
            float rsB = rsqrtf(qb2 * (1.0f / 64.0f) - muB * muB + 1e-5f);
            float g0 = sm_g[lane], g1 = sm_g[lane + 32];
            float t0 = sm_bt[lane], t1 = sm_bt[lane + 32];
            stA(AHc, ALc, s0, lane,      (a0 - muA) * rsA * g0 + t0);
            stA(AHc, ALc, s0, lane + 32, (a1 - muA) * rsA * g1 + t1);
            stA(AHc, ALc, s1, lane,      (b0 - muB) * rsB * g0 + t0);
            stA(AHc, ALc, s1, lane + 32, (b1 - muB) * rsB * g1 + t1);
        }
        hbar(half);

        // ---- P3: QKV mma (head wh), k-paired B loads ----
        float acc[4][3][4];
        #pragma unroll
        for (int mt = 0; mt < 4; mt++)
            #pragma unroll
            for (int g = 0; g < 3; g++)
                #pragma unroll
                for (int i = 0; i < 4; i++) acc[mt][g][i] = 0.f;
        {
            const int arow = lane & 15, acb = (lane >> 4) * 8;
            const int brl = lane & 7, bcol = ((lane >> 3) & 3) * 8;
            const int nbs[3] = {8 * wh, 64 + 8 * wh, 128 + 8 * wh};
            #pragma unroll
            for (int ks2 = 0; ks2 < 2; ks2++) {
                u32 bh2[3][4], bl2[3][4];
                #pragma unroll
                for (int g = 0; g < 3; g++) {
                    u32 off = SWZ((u32)((nbs[g] + brl) * 128 + (ks2 * 32 + bcol) * 2));
                    ldsm4(bh2[g], BQH + off);
                    ldsm4(bl2[g], BQL + off);
                }
                #pragma unroll
                for (int kk = 0; kk < 2; kk++) {
                    int ks = ks2 * 2 + kk;
                    #pragma unroll
                    for (int mt = 0; mt < 4; mt++) {
                        u32 ah[4], al[4];
                        u32 off = SWZ((u32)((mt * 16 + arow) * 128 + (ks * 16 + acb) * 2));
                        ldsm4(ah, AHa + off);
                        ldsm4(al, ALa + off);
                        #pragma unroll
                        for (int g = 0; g < 3; g++) {
                            mmabf(acc[mt][g], ah, bh2[g] + 2 * kk);
                            mmabf(acc[mt][g], ah, bl2[g] + 2 * kk);
                            mmabf(acc[mt][g], al, bh2[g] + 2 * kk);
                        }
                    }
                }
            }
            float bq0, bq1, bk0, bk1, bv0, bv1;
            up2(qbU[4 * wh + gc], bq0, bq1);
            up2(qbU[32 + 4 * wh + gc], bk0, bk1);
            up2(qbU[64 + 4 * wh + gc], bv0, bv1);
            #pragma unroll
            for (int mt = 0; mt < 4; mt++) {
                acc[mt][0][0] += bq0; acc[mt][0][1] += bq1;
                acc[mt][0][2] += bq0; acc[mt][0][3] += bq1;
                acc[mt][1][0] += bk0; acc[mt][1][1] += bk1;
                acc[mt][1][2] += bk0; acc[mt][1][3] += bk1;
                acc[mt][2][0] += bv0; acc[mt][2][1] += bv1;
                acc[mt][2][2] += bv0; acc[mt][2][3] += bv1;
            }
        }

        // V -> t-major bf16 hi/lo tile VT[h][t][d], conflict-free u32 stores
        #pragma unroll
        for (int mt = 0; mt < 4; mt++) {
            float a0 = acc[mt][2][0], a1 = acc[mt][2][1];
            float a2 = acc[mt][2][2], a3 = acc[mt][2][3];
            u32 h0 = bf2(a0, a1);
            u32 l0 = bf2(a0 - bflo(h0), a1 - bfhi(h0));
            u32 h1 = bf2(a2, a3);
            u32 l1 = bf2(a2 - bflo(h1), a3 - bfhi(h1));
            u32 o0 = (u32)(wh * 1024 + (16 * mt + gr) * 16 + gc * 4);
            u32 o1 = o0 + 128;     // row +8
            *(u32*)(VTHc + o0) = h0; *(u32*)(VTLc + o0) = l0;
            *(u32*)(VTHc + o1) = h1; *(u32*)(VTLc + o1) = l1;
        }

        // Q A-frags + K B-frags (hi/lo) in registers
        u32 qh[4][2], ql[4][2], kbh[8], kbl[8];
        #pragma unroll
        for (int mt = 0; mt < 4; mt++) {
            float q0 = acc[mt][0][0], q1 = acc[mt][0][1];
            float q2 = acc[mt][0][2], q3 = acc[mt][0][3];
            qh[mt][0] = bf2(q0, q1);
            ql[mt][0] = bf2(q0 - bflo(qh[mt][0]), q1 - bfhi(qh[mt][0]));
            qh[mt][1] = bf2(q2, q3);
            ql[mt][1] = bf2(q2 - bflo(qh[mt][1]), q3 - bfhi(qh[mt][1]));
            float k0 = acc[mt][1][0], k1 = acc[mt][1][1];
            float k2 = acc[mt][1][2], k3 = acc[mt][1][3];
            kbh[2 * mt]     = bf2(k0, k1);
            kbl[2 * mt]     = bf2(k0 - bflo(kbh[2 * mt]), k1 - bfhi(kbh[2 * mt]));
            kbh[2 * mt + 1] = bf2(k2, k3);
            kbl[2 * mt + 1] = bf2(k2 - bflo(kbh[2 * mt + 1]), k3 - bfhi(kbh[2 * mt + 1]));
        }
        hbar(half);   // A-tile reads done; VT visible; ao may overwrite A tiles

        // ---- P4: attention on tensor cores ----
        {
            // hoisted V B-frags via ldmatrix.trans ([t][d] rows)
            u32 vbh[4][2], vbl[4][2];
            #pragma unroll
            for (int ntp = 0; ntp < 4; ntp++) {
                u32 vo = (u32)(wh * 1024 + (16 * ntp + (lane & 15)) * 16);
                ldsm2t(vbh[ntp], VTHa + vo);
                ldsm2t(vbl[ntp], VTLa + vo);
            }
            #pragma unroll
            for (int mh = 0; mh < 2; mh++) {
                float oacc[2][4];
                float rs[2][2];
                #pragma unroll
                for (int mi = 0; mi < 2; mi++) {
                    oacc[mi][0] = oacc[mi][1] = oacc[mi][2] = oacc[mi][3] = 0.f;
                    rs[mi][0] = rs[mi][1] = 0.f;
                }
                #pragma unroll
                for (int ntp = 0; ntp < 4; ntp++) {
                    #pragma unroll
                    for (int mi = 0; mi < 2; mi++) {
                        int mt = 2 * mh + mi;
                        float s0[4] = {0.f, 0.f, 0.f, 0.f};
                        float s1[4] = {0.f, 0.f, 0.f, 0.f};
                        mmab8(s0, qh[mt], kbh[2 * ntp]);
                        mmab8(s0, ql[mt], kbh[2 * ntp]);
                        mmab8(s0, qh[mt], kbl[2 * ntp]);
                        mmab8(s1, qh[mt], kbh[2 * ntp + 1]);
                        mmab8(s1, ql[mt], kbh[2 * ntp + 1]);
                        mmab8(s1, qh[mt], kbl[2 * ntp + 1]);
                        int idx = ((mt * 4 + ntp) * 32 + lane) * 2;
                        float4 f0 = cbF4[idx], f1 = cbF4[idx + 1];
                        float p00 = ex2_(fmaf(s0[0], KSCALE, f0.x));
                        float p01 = ex2_(fmaf(s0[1], KSCALE, f0.y));
                        float p02 = ex2_(fmaf(s0[2], KSCALE, f0.z));
                        float p03 = ex2_(fmaf(s0[3], KSCALE, f0.w));
                        float p10 = ex2_(fmaf(s1[0], KSCALE, f1.x));
                        float p11 = ex2_(fmaf(s1[1], KSCALE, f1.y));
                        float p12 = ex2_(fmaf(s1[2], KSCALE, f1.z));
                        float p13 = ex2_(fmaf(s1[3], KSCALE, f1.w));
                        rs[mi][0] += (p00 + p01) + (p10 + p11);
                        rs[mi][1] += (p02 + p03) + (p12 + p13);
                        u32 pa[4], pl_[4];
                        pa[0] = bf2(p00, p01);
                        pa[1] = bf2(p02, p03);
                        pa[2] = bf2(p10, p11);
                        pa[3] = bf2(p12, p13);
                        pl_[0] = bf2(p00 - bflo(pa[0]), p01 - bfhi(pa[0]));
                        pl_[1] = bf2(p02 - bflo(pa[1]), p03 - bfhi(pa[1]));
                        pl_[2] = bf2(p10 - bflo(pa[2]), p11 - bfhi(pa[2]));
                        pl_[3] = bf2(p12 - bflo(pa[3]), p13 - bfhi(pa[3]));
                        mmabf(oacc[mi], pa, vbh[ntp]);
                        mmabf(oacc[mi], pl_, vbh[ntp]);
                        mmabf(oacc[mi], pa, vbl[ntp]);
                    }
                }
                #pragma unroll
                for (int mi = 0; mi < 2; mi++) {
                    int r0 = 16 * (2 * mh + mi) + gr;
                    float ra = rs[mi][0], rb2 = rs[mi][1];
                    ra  += __shfl_xor_sync(0xffffffffu, ra, 1);
                    ra  += __shfl_xor_sync(0xffffffffu, ra, 2);
                    rb2 += __shfl_xor_sync(0xffffffffu, rb2, 1);
                    rb2 += __shfl_xor_sync(0xffffffffu, rb2, 2);
                    float i0 = 1.0f / ra, i1 = 1.0f / rb2;
                    float o0 = oacc[mi][0] * i0, o1 = oacc[mi][1] * i0;
                    float o2 = oacc[mi][2] * i1, o3 = oacc[mi][3] * i1;
                    u32 h0 = bf2(o0, o1);
                    u32 l0 = bf2(o0 - bflo(h0), o1 - bfhi(h0));
                    u32 h1 = bf2(o2, o3);
                    u32 l1 = bf2(o2 - bflo(h1), o3 - bfhi(h1));
                    u32 co = (u32)((8 * wh + 2 * gc) * 2);
                    *(u32*)(AHc + SWZ((u32)(r0 * 128) + co)) = h0;
                    *(u32*)(ALc + SWZ((u32)(r0 * 128) + co)) = l0;
                    *(u32*)(AHc + SWZ((u32)((r0 + 8) * 128) + co)) = h1;
                    *(u32*)(ALc + SWZ((u32)((r0 + 8) * 128) + co)) = l1;
                }
            }
        }
        hbar(half);

        // next-batch counter fetch (hidden behind P5)
        if (tidh == 0) sm_bb[half] = atomicAdd(&g_next_batch, 1);

        // ---- P5: out-proj via mma.sync (mt = wh&3, nh = wh>>2), k-paired B ----
        {
            const int mt = wh & 3, nh = wh >> 2;
            float oa[4][4];
            #pragma unroll
            for (int nt = 0; nt < 4; nt++)
                #pragma unroll
                for (int i = 0; i < 4; i++) oa[nt][i] = 0.f;
            const int arow = lane & 15, acb = (lane >> 4) * 8;
            const int brl = lane & 7, bcol = ((lane >> 3) & 3) * 8;
            #pragma unroll
            for (int ks2 = 0; ks2 < 2; ks2++) {
                u32 bh2[4][4], bl2[4][4];
                #pragma unroll
                for (int nt = 0; nt < 4; nt++) {
                    u32 boff = SWZ((u32)((nh * 32 + nt * 8 + brl) * 128 + (ks2 * 32 + bcol) * 2));
                    ldsm4(bh2[nt], BOH + boff);
                    ldsm4(bl2[nt], BOL + boff);
                }
                #pragma unroll
                for (int kk = 0; kk < 2; kk++) {
                    int ks = ks2 * 2 + kk;
                    u32 ah[4], al[4];
                    u32 off = SWZ((u32)((mt * 16 + arow) * 128 + (ks * 16 + acb) * 2));
                    ldsm4(ah, AHa + off);
                    ldsm4(al, ALa + off);
                    #pragma unroll
                    for (int nt = 0; nt < 4; nt++) {
                        mmabf(oa[nt], ah, bh2[nt] + 2 * kk);
                        mmabf(oa[nt], ah, bl2[nt] + 2 * kk);
                        mmabf(oa[nt], al, bh2[nt] + 2 * kk);
                    }
                }
            }
            #pragma unroll
            for (int nt = 0; nt < 4; nt++) {
                int e0 = nh * 32 + nt * 8 + 2 * gc;
                int s0 = mt * 16 + gr;
                float ob0 = sm_ob[e0], ob1 = sm_ob[e0 + 1];
                yT[e0 * 65 + s0]           = oa[nt][0] + ob0;
                yT[(e0 + 1) * 65 + s0]     = oa[nt][1] + ob1;
                yT[e0 * 65 + s0 + 8]       = oa[nt][2] + ob0;
                yT[(e0 + 1) * 65 + s0 + 8] = oa[nt][3] + ob1;
            }
        }
        hbar(half);

        // ---- P6: residual (xst = x+pos) + yT -> out ----
        float4* ob4 = (float4*)(gout + (size_t)b * 4096);
        #pragma unroll
        for (int it = 0; it < 4; it++) {
            int i4 = tidh + 256 * it;
            int e = i4 >> 4, s0 = (i4 & 15) * 4;
            const float* xp = xst + e * 65 + s0;
            const float* yp = yT + e * 65 + s0;
            float4 o;
            o.x = xp[0] + yp[0];
            o.y = xp[1] + yp[1];
            o.z = xp[2] + yp[2];
            o.w = xp[3] + yp[3];
            ob4[i4] = o;
        }
        b = sm_bb[half];
        hbar(half);       // protect xst/yT/VT/A reuse + sm_bb slot
    }
}

extern "C" void kernel_launch(void* const* d_in, const int* in_sizes, int n_in,
                              void* d_out, int out_size)
{
    (void)in_sizes; (void)n_in; (void)out_size;
    cudaFuncSetAttribute(chess_attn_kernel,
                         cudaFuncAttributeMaxDynamicSharedMemorySize, SMEM_BYTES);
    hx_reset_counter<<<1, 1>>>();
    chess_attn_kernel<<<152, TPB, SMEM_BYTES>>>(
        (const float*)d_in[0], (const float*)d_in[1], (const float*)d_in[2],
        (const float*)d_in[3], (const float*)d_in[4], (const float*)d_in[5],
        (const float*)d_in[6], (const float*)d_in[7], (const float*)d_in[8],
        (float*)d_out);
}